// round 1
// baseline (speedup 1.0000x reference)
#include <cuda_runtime.h>
#include <cstdint>
#include <cstddef>

#define QLEN 1024
#define BSZ 4
#define DM 1024
#define NH 16
#define DH 64
#define BN_TOT 64   // BSZ*NH
#define NEGINF -1e30f

// ---------------- scratch (device globals; no allocation) ----------------
__device__ float g_heads[(size_t)QLEN * BSZ * 3 * DM];      // [i*4+b][3072]
__device__ float g_rk[(size_t)QLEN * DM];                   // [m][1024]
__device__ float g_qw[(size_t)BN_TOT * QLEN * DH];          // [bn][i][d]  q + r_w_bias
__device__ float g_qr[(size_t)BN_TOT * QLEN * DH];          // [bn][i][d]  q + r_r_bias
__device__ float g_kt[(size_t)BN_TOT * DH * QLEN];          // [bn][d][j]
__device__ float g_vc[(size_t)BN_TOT * QLEN * DH];          // [bn][j][d]
__device__ float g_rkt[(size_t)NH * DH * QLEN];             // [n][d][m]
__device__ float g_score[(size_t)BN_TOT * QLEN * QLEN];     // [bn][i][j] -> becomes prob
__device__ float g_vec[(size_t)QLEN * BSZ * DM];            // [i*4+b][n*64+d]
__device__ float g_attn[(size_t)QLEN * BSZ * DM];

// ---------------- generic tiled SGEMM (row-major, batched) ----------------
template <int BM, int BN, int BK, int TM, int TN>
__global__ __launch_bounds__((BM / TM) * (BN / TN)) void sgemm_kernel(
    const float* __restrict__ A, const float* __restrict__ B, float* __restrict__ C,
    int M, int N, int K, int lda, int ldb, int ldc,
    long long sA, long long sB, long long sC)
{
    constexpr int THREADS = (BM / TM) * (BN / TN);
    __shared__ float As[BK][BM];
    __shared__ float Bs[BK][BN];

    int bz = blockIdx.z;
    A += (size_t)bz * sA;
    B += (size_t)bz * sB;
    C += (size_t)bz * sC;

    int bm = blockIdx.y * BM;
    int bn = blockIdx.x * BN;
    int tid = threadIdx.x;
    int tc = tid % (BN / TN);
    int tr = tid / (BN / TN);

    float acc[TM][TN];
#pragma unroll
    for (int i = 0; i < TM; i++)
#pragma unroll
        for (int j = 0; j < TN; j++) acc[i][j] = 0.f;

    constexpr int ALOADS = BM * BK / THREADS;
    constexpr int BLOADS = BK * BN / THREADS;

    for (int k0 = 0; k0 < K; k0 += BK) {
#pragma unroll
        for (int i = 0; i < ALOADS; i++) {
            int e = tid + i * THREADS;
            int r = e / BK, c = e % BK;
            As[c][r] = A[(size_t)(bm + r) * lda + k0 + c];
        }
#pragma unroll
        for (int i = 0; i < BLOADS; i++) {
            int e = tid + i * THREADS;
            int r = e / BN, c = e % BN;
            Bs[r][c] = B[(size_t)(k0 + r) * ldb + bn + c];
        }
        __syncthreads();

#pragma unroll
        for (int kk = 0; kk < BK; kk++) {
            float ra[TM], rb[TN];
#pragma unroll
            for (int i = 0; i < TM; i++) ra[i] = As[kk][tr * TM + i];
#pragma unroll
            for (int j = 0; j < TN; j++) rb[j] = Bs[kk][tc * TN + j];
#pragma unroll
            for (int i = 0; i < TM; i++)
#pragma unroll
                for (int j = 0; j < TN; j++) acc[i][j] += ra[i] * rb[j];
        }
        __syncthreads();
    }

#pragma unroll
    for (int i = 0; i < TM; i++)
#pragma unroll
        for (int j = 0; j < TN; j++)
            C[(size_t)(bm + tr * TM + i) * ldc + bn + tc * TN + j] = acc[i][j];
}

// ---------------- pack kernels ----------------
__global__ void pack_q_kernel(const float* __restrict__ rwb, const float* __restrict__ rrb)
{
    int idx = blockIdx.x * 256 + threadIdx.x;          // over 64*1024*64
    int d = idx & 63;
    int i = (idx >> 6) & 1023;
    int bn = idx >> 16;
    int b = bn >> 4, n = bn & 15;
    float q = g_heads[(size_t)(i * 4 + b) * 3072 + n * 64 + d];
    g_qw[idx] = q + rwb[n * 64 + d];
    g_qr[idx] = q + rrb[n * 64 + d];
}

__global__ void pack_kv_kernel()
{
    int idx = blockIdx.x * 256 + threadIdx.x;          // over 64*64*1024
    {   // Kt: [bn][d][j]
        int j = idx & 1023;
        int d = (idx >> 10) & 63;
        int bn = idx >> 16;
        int b = bn >> 4, n = bn & 15;
        g_kt[idx] = g_heads[(size_t)(j * 4 + b) * 3072 + 1024 + n * 64 + d];
    }
    {   // Vc: [bn][j][d]
        int d = idx & 63;
        int j = (idx >> 6) & 1023;
        int bn = idx >> 16;
        int b = bn >> 4, n = bn & 15;
        g_vc[idx] = g_heads[(size_t)(j * 4 + b) * 3072 + 2048 + n * 64 + d];
    }
}

__global__ void pack_rk_kernel()
{
    int idx = blockIdx.x * 256 + threadIdx.x;          // over 16*64*1024
    int m = idx & 1023;
    int d = (idx >> 10) & 63;
    int n = idx >> 16;
    g_rkt[idx] = g_rk[(size_t)m * 1024 + n * 64 + d];
}

// ---------------- fused score kernel: AC + rel-shifted BD + mask + scale ----------------
// score[bn][i][j] = 0.125 * ( (q_i+rwb).k_j + (q_i+rrb).r_k[j-i+1023] ), causal tiles only
__global__ __launch_bounds__(256) void score_kernel()
{
    int jt = blockIdx.x, it = blockIdx.y, bn = blockIdx.z;
    int i0 = it * 64, j0 = jt * 64;
    if (j0 > i0 + 63) return;                          // fully masked tile, never read
    int n = bn & 15;

    extern __shared__ float sm[];
    float* Qw_s = sm;                                  // [64][64]
    float* Qr_s = sm + 4096;                           // [64][64]
    float* Kt_s = sm + 8192;                           // [d][64]
    float* Rk_s = sm + 12288;                          // [d][128] (127 used)

    int tid = threadIdx.x;
    const float* qwB = g_qw + (size_t)bn * QLEN * DH;
    const float* qrB = g_qr + (size_t)bn * QLEN * DH;
    const float* ktB = g_kt + (size_t)bn * DH * QLEN;
    const float* rkB = g_rkt + (size_t)n * DH * QLEN;

    for (int e = tid; e < 4096; e += 256) {
        int r = e >> 6, c = e & 63;
        Qw_s[e] = qwB[(size_t)(i0 + r) * 64 + c];
        Qr_s[e] = qrB[(size_t)(i0 + r) * 64 + c];
        Kt_s[e] = ktB[(size_t)r * QLEN + j0 + c];      // r = d, c = j
    }
    int mb = j0 - i0 + 960;                            // m = mb + t, t in [0,126]
    for (int e = tid; e < 64 * 127; e += 256) {
        int d = e / 127, t = e % 127;
        int m = mb + t;
        Rk_s[d * 128 + t] = (m >= 0 && m < QLEN) ? rkB[(size_t)d * QLEN + m] : 0.f;
    }
    __syncthreads();

    int tc = tid & 15, tr = tid >> 4;
    int ii0 = tr * 4, jj0 = tc * 4;
    int tb = jj0 - ii0 + 63;                           // band idx for (i',j') is tb + j' - i'

    float acc[4][4];
#pragma unroll
    for (int i = 0; i < 4; i++)
#pragma unroll
        for (int j = 0; j < 4; j++) acc[i][j] = 0.f;

    for (int d = 0; d < 64; d++) {
        float qw[4], qr[4], kk[4], rk[7];
#pragma unroll
        for (int i = 0; i < 4; i++) {
            qw[i] = Qw_s[(ii0 + i) * 64 + d];
            qr[i] = Qr_s[(ii0 + i) * 64 + d];
        }
#pragma unroll
        for (int j = 0; j < 4; j++) kk[j] = Kt_s[d * 64 + jj0 + j];
#pragma unroll
        for (int t = 0; t < 7; t++) rk[t] = Rk_s[d * 128 + tb - 3 + t];
#pragma unroll
        for (int i = 0; i < 4; i++)
#pragma unroll
            for (int j = 0; j < 4; j++)
                acc[i][j] += qw[i] * kk[j] + qr[i] * rk[3 + j - i];
    }

    size_t base = (size_t)bn * QLEN * QLEN;
#pragma unroll
    for (int i = 0; i < 4; i++) {
        int gi = i0 + ii0 + i;
#pragma unroll
        for (int j = 0; j < 4; j++) {
            int gj = j0 + jj0 + j;
            float v = (gj <= gi) ? acc[i][j] * 0.125f : NEGINF;
            g_score[base + (size_t)gi * QLEN + gj] = v;
        }
    }
}

// ---------------- causal softmax (in-place score -> prob, zeros for j>i) ----------------
__global__ __launch_bounds__(256) void softmax_kernel()
{
    int row = blockIdx.x;                              // bn*1024 + i
    int i = row & 1023;
    float* p = g_score + (size_t)row * QLEN;
    int klen = i + 1;
    int tid = threadIdx.x;

    __shared__ float red[256];

    float mx = NEGINF;
    for (int j = tid; j < klen; j += 256) mx = fmaxf(mx, p[j]);
    red[tid] = mx;
    __syncthreads();
    for (int s = 128; s > 0; s >>= 1) {
        if (tid < s) red[tid] = fmaxf(red[tid], red[tid + s]);
        __syncthreads();
    }
    mx = red[0];
    __syncthreads();

    float sum = 0.f;
    for (int j = tid; j < klen; j += 256) {
        float e = __expf(p[j] - mx);
        p[j] = e;
        sum += e;
    }
    red[tid] = sum;
    __syncthreads();
    for (int s = 128; s > 0; s >>= 1) {
        if (tid < s) red[tid] += red[tid + s];
        __syncthreads();
    }
    float inv = 1.f / red[0];

    for (int j = tid; j < klen; j += 256) p[j] *= inv;
    for (int j = klen + tid; j < QLEN; j += 256) p[j] = 0.f;
}

// ---------------- residual + layernorm ----------------
__global__ __launch_bounds__(256) void ln_kernel(
    const float* __restrict__ w, const float* __restrict__ gamma,
    const float* __restrict__ beta, float* __restrict__ out)
{
    int row = blockIdx.x;                              // 4096 rows
    const float* wr = w + (size_t)row * DM;
    const float* ar = g_attn + (size_t)row * DM;
    int tid = threadIdx.x;

    float x[4];
    float s = 0.f, s2 = 0.f;
#pragma unroll
    for (int u = 0; u < 4; u++) {
        int c = tid + u * 256;
        x[u] = wr[c] + ar[c];
        s += x[u];
        s2 += x[u] * x[u];
    }
    __shared__ float rs[256], rs2[256];
    rs[tid] = s; rs2[tid] = s2;
    __syncthreads();
    for (int t = 128; t > 0; t >>= 1) {
        if (tid < t) { rs[tid] += rs[tid + t]; rs2[tid] += rs2[tid + t]; }
        __syncthreads();
    }
    float mu = rs[0] * (1.f / DM);
    float var = rs2[0] * (1.f / DM) - mu * mu;
    float rstd = rsqrtf(var + 1e-5f);
#pragma unroll
    for (int u = 0; u < 4; u++) {
        int c = tid + u * 256;
        out[(size_t)row * DM + c] = (x[u] - mu) * rstd * gamma[c] + beta[c];
    }
}

// ---------------- launch ----------------
extern "C" void kernel_launch(void* const* d_in, const int* in_sizes, int n_in,
                              void* d_out, int out_size)
{
    const float* w     = (const float*)d_in[0];   // [1024,4,1024]
    const float* r     = (const float*)d_in[1];   // [1024,1024]
    const float* rwb   = (const float*)d_in[2];   // [16,64]
    const float* rrb   = (const float*)d_in[3];   // [16,64]
    // d_in[4] attn_mask: deterministically causal — handled analytically
    const float* W_qkv = (const float*)d_in[5];   // [1024,3072]
    const float* W_r   = (const float*)d_in[6];   // [1024,1024]
    const float* W_o   = (const float*)d_in[7];   // [1024,1024]
    const float* gamma = (const float*)d_in[8];
    const float* beta  = (const float*)d_in[9];
    float* out = (float*)d_out;

    float *p_heads, *p_rk, *p_score, *p_vc, *p_vec, *p_attn;
    cudaGetSymbolAddress((void**)&p_heads, g_heads);
    cudaGetSymbolAddress((void**)&p_rk, g_rk);
    cudaGetSymbolAddress((void**)&p_score, g_score);
    cudaGetSymbolAddress((void**)&p_vc, g_vc);
    cudaGetSymbolAddress((void**)&p_vec, g_vec);
    cudaGetSymbolAddress((void**)&p_attn, g_attn);

    static int smem_set = 0;
    if (!smem_set) {
        cudaFuncSetAttribute(score_kernel, cudaFuncAttributeMaxDynamicSharedMemorySize, 81920);
        smem_set = 1;
    }

    // 1) heads = w @ W_qkv   [4096 x 3072 x 1024]
    sgemm_kernel<128, 128, 8, 8, 8><<<dim3(3072 / 128, 4096 / 128, 1), 256>>>(
        w, W_qkv, p_heads, 4096, 3072, 1024, 1024, 3072, 3072, 0, 0, 0);

    // 2) r_k = r @ W_r   [1024 x 1024 x 1024]
    sgemm_kernel<128, 128, 8, 8, 8><<<dim3(1024 / 128, 1024 / 128, 1), 256>>>(
        r, W_r, p_rk, 1024, 1024, 1024, 1024, 1024, 1024, 0, 0, 0);

    // 3) pack
    pack_q_kernel<<<BN_TOT * QLEN * DH / 256, 256>>>(rwb, rrb);
    pack_kv_kernel<<<BN_TOT * QLEN * DH / 256, 256>>>();
    pack_rk_kernel<<<NH * DH * QLEN / 256, 256>>>();

    // 4) fused scores (causal tiles only)
    score_kernel<<<dim3(16, 16, BN_TOT), 256, 81920>>>();

    // 5) causal softmax (in-place)
    softmax_kernel<<<BN_TOT * QLEN, 256>>>();

    // 6) vec = prob @ V   batched over bn: [1024 x 64 x 1024] x64
    sgemm_kernel<128, 64, 8, 8, 4><<<dim3(1, 1024 / 128, BN_TOT), 256>>>(
        p_score, p_vc, p_vec, 1024, 64, 1024, 1024, 64, 4096,
        (long long)QLEN * QLEN, (long long)QLEN * DH, 64);

    // 7) attn = vec @ W_o   [4096 x 1024 x 1024]
    sgemm_kernel<128, 128, 8, 8, 8><<<dim3(1024 / 128, 4096 / 128, 1), 256>>>(
        p_vec, W_o, p_attn, 4096, 1024, 1024, 1024, 1024, 1024, 0, 0, 0);

    // 8) out = layernorm(w + attn)
    ln_kernel<<<4096, 256>>>(w, gamma, beta, out);
}

// round 3
// speedup vs baseline: 1.5872x; 1.5872x over previous
#include <cuda_runtime.h>
#include <cuda_bf16.h>
#include <cstdint>
#include <cstddef>

#define QLEN 1024
#define BSZ 4
#define DM 1024
#define NH 16
#define DH 64
#define BN_TOT 64
#define NEGINF -1e30f
#define KDIM 1024

__device__ __forceinline__ uint32_t smem_to_u32(const void* p) {
    uint32_t a;
    asm("{ .reg .u64 t; cvta.to.shared.u64 t, %1; cvt.u32.u64 %0, t; }" : "=r"(a) : "l"(p));
    return a;
}
#define SWZ128(b) ((b) ^ (((b) >> 3) & 0x70))

__device__ __forceinline__ void ldm_x4(uint32_t r[4], uint32_t addr) {
    asm volatile("ldmatrix.sync.aligned.m8n8.x4.shared.b16 {%0,%1,%2,%3}, [%4];"
                 : "=r"(r[0]), "=r"(r[1]), "=r"(r[2]), "=r"(r[3]) : "r"(addr));
}
__device__ __forceinline__ void mma16816(float c[4], const uint32_t a[4], const uint32_t b[2]) {
    asm volatile("mma.sync.aligned.m16n8k16.row.col.f32.bf16.bf16.f32 "
                 "{%0,%1,%2,%3}, {%4,%5,%6,%7}, {%8,%9}, {%0,%1,%2,%3};"
                 : "+f"(c[0]), "+f"(c[1]), "+f"(c[2]), "+f"(c[3])
                 : "r"(a[0]), "r"(a[1]), "r"(a[2]), "r"(a[3]), "r"(b[0]), "r"(b[1]));
}

// ---------------- scratch ----------------
__device__ float g_heads[(size_t)QLEN * BSZ * 3 * DM];
__device__ float g_rk[(size_t)QLEN * DM];
__device__ float g_qw[(size_t)BN_TOT * QLEN * DH];
__device__ float g_qr[(size_t)BN_TOT * QLEN * DH];
__device__ float g_kt[(size_t)BN_TOT * DH * QLEN];
__device__ float g_rkt[(size_t)NH * DH * QLEN];
__device__ float g_score[(size_t)BN_TOT * QLEN * QLEN];
__device__ float g_pv[(size_t)BN_TOT * QLEN * DH];
__device__ float g_attn[(size_t)QLEN * BSZ * DM];
__device__ __nv_bfloat16 g_wbf[(size_t)QLEN * BSZ * 2 * KDIM];
__device__ __nv_bfloat16 g_rbf[(size_t)QLEN * 2 * KDIM];
__device__ __nv_bfloat16 g_qkvt[(size_t)3 * DM * 2 * KDIM];
__device__ __nv_bfloat16 g_wrt[(size_t)DM * 2 * KDIM];
__device__ __nv_bfloat16 g_wot[(size_t)DM * 2 * KDIM];
__device__ __nv_bfloat16 g_vtbf[(size_t)BN_TOT * DH * 2 * QLEN];
__device__ __nv_bfloat16 g_probbf[(size_t)BN_TOT * QLEN * 2 * QLEN];
__device__ __nv_bfloat16 g_vecbf[(size_t)QLEN * BSZ * 2 * KDIM];

__device__ __forceinline__ void split2(float x, __nv_bfloat16& h, __nv_bfloat16& l) {
    h = __float2bfloat16(x);
    l = __float2bfloat16(x - __bfloat162float(h));
}

// ---------------- HMMA GEMM: C[M,N] = A[M,2K] x Bt[N,2K] (3-term hi/lo) ----------------
// BM = 128 fixed. Stage = K-chunk of 64 bf16 (128B rows), double-buffered, SW128 swizzle.
template <int BM, int BN>
__global__ __launch_bounds__(256) void mma_gemm(
    const __nv_bfloat16* __restrict__ A, const __nv_bfloat16* __restrict__ Bt,
    float* __restrict__ C, int K, int lda, int ldb, int ldc,
    long long sA, long long sB, long long sC)
{
    extern __shared__ char smem[];
    const uint32_t smem_u32 = smem_to_u32(smem);
    constexpr int ASZ = BM * 128;          // bytes per A stage
    constexpr int BSZ_ = BN * 128;         // bytes per B stage
    constexpr int A_OFF = 0;
    constexpr int B_OFF = 2 * ASZ;
    constexpr int ACH = BM / 32;           // uint4 chunks per thread
    constexpr int BCH = BN / 32;
    constexpr int WN = BN / 2;             // warp n-extent (4x2 warp grid)
    constexpr int MT = 2;                  // m16 tiles per warp (warp m-extent 32)
    constexpr int NT = WN / 8;             // n8 tiles per warp

    const int tid = threadIdx.x;
    const int lane = tid & 31, warp = tid >> 5;
    const int wm = warp & 3, wn = warp >> 2;
    const int bz = blockIdx.z;
    const int m0 = blockIdx.y * BM;
    const int n0 = blockIdx.x * BN;
    const __nv_bfloat16* Ab = A + (size_t)bz * sA;
    const __nv_bfloat16* Bb = Bt + (size_t)bz * sB;
    float* Cb = C + (size_t)bz * sC;

    const int KT = K / 64;
    const int T = 3 * KT;

    uint4 ra[ACH], rb[BCH];
    auto ldg_tile = [&](int t) {
        int p = t / KT, kt = t - p * KT;
        int aoff = ((p == 1) ? K : 0) + kt * 64;
        int boff = ((p == 2) ? K : 0) + kt * 64;
#pragma unroll
        for (int i = 0; i < ACH; i++) {
            int c = tid + i * 256, row = c >> 3, q = c & 7;
            ra[i] = *(const uint4*)(Ab + (size_t)(m0 + row) * lda + aoff + q * 8);
        }
#pragma unroll
        for (int i = 0; i < BCH; i++) {
            int c = tid + i * 256, row = c >> 3, q = c & 7;
            rb[i] = *(const uint4*)(Bb + (size_t)(n0 + row) * ldb + boff + q * 8);
        }
    };
    auto sts_tile = [&](int s) {
#pragma unroll
        for (int i = 0; i < ACH; i++) {
            int c = tid + i * 256, row = c >> 3, q = c & 7;
            int b = SWZ128(row * 128 + q * 16);
            *(uint4*)(smem + A_OFF + s * ASZ + b) = ra[i];
        }
#pragma unroll
        for (int i = 0; i < BCH; i++) {
            int c = tid + i * 256, row = c >> 3, q = c & 7;
            int b = SWZ128(row * 128 + q * 16);
            *(uint4*)(smem + B_OFF + s * BSZ_ + b) = rb[i];
        }
    };

    float acc[MT][NT][4];
#pragma unroll
    for (int mt = 0; mt < MT; mt++)
#pragma unroll
        for (int nt = 0; nt < NT; nt++)
#pragma unroll
            for (int u = 0; u < 4; u++) acc[mt][nt][u] = 0.f;

    ldg_tile(0);
    sts_tile(0);
    __syncthreads();

    for (int t = 0; t < T; t++) {
        const int s = t & 1;
        const bool more = (t + 1 < T);
        if (more) ldg_tile(t + 1);

        const uint32_t abase = smem_u32 + A_OFF + s * ASZ;
        const uint32_t bbase = smem_u32 + B_OFF + s * BSZ_;
#pragma unroll
        for (int kk = 0; kk < 4; kk++) {
            const int seg = kk * 32 + (lane >> 4) * 16;
            uint32_t af[MT][4], bf[NT][2];
#pragma unroll
            for (int mt = 0; mt < MT; mt++) {
                int row = wm * 32 + mt * 16 + (lane & 15);
                ldm_x4(af[mt], abase + SWZ128(row * 128 + seg));
            }
#pragma unroll
            for (int p = 0; p < NT / 2; p++) {
                int row = wn * WN + p * 16 + (lane & 15);
                uint32_t r[4];
                ldm_x4(r, bbase + SWZ128(row * 128 + seg));
                bf[2 * p][0] = r[0]; bf[2 * p][1] = r[2];
                bf[2 * p + 1][0] = r[1]; bf[2 * p + 1][1] = r[3];
            }
#pragma unroll
            for (int mt = 0; mt < MT; mt++)
#pragma unroll
                for (int nt = 0; nt < NT; nt++)
                    mma16816(acc[mt][nt], af[mt], bf[nt]);
        }
        __syncthreads();
        if (more) {
            sts_tile((t + 1) & 1);
            __syncthreads();
        }
    }

    // epilogue: registers -> C
#pragma unroll
    for (int mt = 0; mt < MT; mt++) {
#pragma unroll
        for (int nt = 0; nt < NT; nt++) {
            int mrow = m0 + wm * 32 + mt * 16 + (lane >> 2);
            int col = n0 + wn * WN + nt * 8 + (lane & 3) * 2;
            *(float2*)&Cb[(size_t)mrow * ldc + col] = make_float2(acc[mt][nt][0], acc[mt][nt][1]);
            *(float2*)&Cb[(size_t)(mrow + 8) * ldc + col] = make_float2(acc[mt][nt][2], acc[mt][nt][3]);
        }
    }
}

// ---------------- split / transpose kernels ----------------
__global__ void split_kernel(const float* __restrict__ X, __nv_bfloat16* __restrict__ Y, int cols)
{
    int idx = blockIdx.x * 256 + threadIdx.x;
    int row = idx / cols, col = idx - row * cols;
    __nv_bfloat16 h, l;
    split2(X[idx], h, l);
    Y[(size_t)row * 2 * cols + col] = h;
    Y[(size_t)row * 2 * cols + cols + col] = l;
}

// X [K][N] row-major -> Y [N][2K] (hi | lo)
__global__ __launch_bounds__(256) void tsplit_kernel(const float* __restrict__ X,
                                                     __nv_bfloat16* __restrict__ Y, int N, int K)
{
    __shared__ float sm[64][65];
    int k0 = blockIdx.x * 64, n0 = blockIdx.y * 64;
    int tid = threadIdx.x;
    for (int e = tid; e < 4096; e += 256) {
        int r = e >> 6, c = e & 63;
        sm[c][r] = X[(size_t)(k0 + r) * N + n0 + c];
    }
    __syncthreads();
    for (int e = tid; e < 4096; e += 256) {
        int r = e >> 6, c = e & 63;
        __nv_bfloat16 h, l;
        split2(sm[r][c], h, l);
        Y[(size_t)(n0 + r) * 2 * K + k0 + c] = h;
        Y[(size_t)(n0 + r) * 2 * K + K + k0 + c] = l;
    }
}

__global__ void pack_q_kernel(const float* __restrict__ rwb, const float* __restrict__ rrb)
{
    int idx = blockIdx.x * 256 + threadIdx.x;
    int d = idx & 63, i = (idx >> 6) & 1023, bn = idx >> 16;
    int b = bn >> 4, n = bn & 15;
    float q = g_heads[(size_t)(i * 4 + b) * 3072 + n * 64 + d];
    g_qw[idx] = q + rwb[n * 64 + d];
    g_qr[idx] = q + rrb[n * 64 + d];
}

__global__ void pack_kt_kernel()
{
    int idx = blockIdx.x * 256 + threadIdx.x;
    int j = idx & 1023, d = (idx >> 10) & 63, bn = idx >> 16;
    int b = bn >> 4, n = bn & 15;
    g_kt[idx] = g_heads[(size_t)(j * 4 + b) * 3072 + 1024 + n * 64 + d];
}

__global__ __launch_bounds__(256) void pack_vt_kernel()
{
    __shared__ float sm[64][65];
    int bn = blockIdx.y, b = bn >> 4, n = bn & 15;
    int j0 = blockIdx.x * 64;
    int tid = threadIdx.x;
    for (int e = tid; e < 4096; e += 256) {
        int jj = e >> 6, d = e & 63;
        sm[d][jj] = g_heads[(size_t)((j0 + jj) * 4 + b) * 3072 + 2048 + n * 64 + d];
    }
    __syncthreads();
    for (int e = tid; e < 4096; e += 256) {
        int d = e >> 6, jj = e & 63;
        __nv_bfloat16 h, l;
        split2(sm[d][jj], h, l);
        g_vtbf[((size_t)bn * 64 + d) * 2048 + j0 + jj] = h;
        g_vtbf[((size_t)bn * 64 + d) * 2048 + 1024 + j0 + jj] = l;
    }
}

__global__ void pack_rk_kernel()
{
    int idx = blockIdx.x * 256 + threadIdx.x;
    int m = idx & 1023, d = (idx >> 10) & 63, n = idx >> 16;
    g_rkt[idx] = g_rk[(size_t)m * 1024 + n * 64 + d];
}

__global__ void vec_split_kernel()
{
    int idx = blockIdx.x * 256 + threadIdx.x;
    int d = idx & 63, i = (idx >> 6) & 1023, bn = idx >> 16;
    int b = bn >> 4, n = bn & 15;
    __nv_bfloat16 h, l;
    split2(g_pv[idx], h, l);
    size_t row = (size_t)(i * 4 + b) * 2048;
    g_vecbf[row + n * 64 + d] = h;
    g_vecbf[row + 1024 + n * 64 + d] = l;
}

// ---------------- fused score kernel (fp32): AC + shifted BD + mask + scale ----------------
__global__ __launch_bounds__(256) void score_kernel()
{
    int jt = blockIdx.x, it = blockIdx.y, bn = blockIdx.z;
    int i0 = it * 64, j0 = jt * 64;
    if (j0 > i0 + 63) return;
    int n = bn & 15;

    extern __shared__ float sm[];
    float* Qw_s = sm;
    float* Qr_s = sm + 4096;
    float* Kt_s = sm + 8192;
    float* Rk_s = sm + 12288;

    int tid = threadIdx.x;
    const float* qwB = g_qw + (size_t)bn * QLEN * DH;
    const float* qrB = g_qr + (size_t)bn * QLEN * DH;
    const float* ktB = g_kt + (size_t)bn * DH * QLEN;
    const float* rkB = g_rkt + (size_t)n * DH * QLEN;

    for (int e = tid; e < 4096; e += 256) {
        int r = e >> 6, c = e & 63;
        Qw_s[e] = qwB[(size_t)(i0 + r) * 64 + c];
        Qr_s[e] = qrB[(size_t)(i0 + r) * 64 + c];
        Kt_s[e] = ktB[(size_t)r * QLEN + j0 + c];
    }
    int mb = j0 - i0 + 960;
    for (int e = tid; e < 64 * 127; e += 256) {
        int d = e / 127, t = e % 127;
        int m = mb + t;
        Rk_s[d * 128 + t] = (m >= 0 && m < QLEN) ? rkB[(size_t)d * QLEN + m] : 0.f;
    }
    __syncthreads();

    int tc = tid & 15, tr = tid >> 4;
    int ii0 = tr * 4, jj0 = tc * 4;
    int tb = jj0 - ii0 + 63;

    float acc[4][4];
#pragma unroll
    for (int i = 0; i < 4; i++)
#pragma unroll
        for (int j = 0; j < 4; j++) acc[i][j] = 0.f;

    for (int d = 0; d < 64; d++) {
        float qw[4], qr[4], kk[4], rk[7];
#pragma unroll
        for (int i = 0; i < 4; i++) {
            qw[i] = Qw_s[(ii0 + i) * 64 + d];
            qr[i] = Qr_s[(ii0 + i) * 64 + d];
        }
#pragma unroll
        for (int j = 0; j < 4; j++) kk[j] = Kt_s[d * 64 + jj0 + j];
#pragma unroll
        for (int t = 0; t < 7; t++) rk[t] = Rk_s[d * 128 + tb - 3 + t];
#pragma unroll
        for (int i = 0; i < 4; i++)
#pragma unroll
            for (int j = 0; j < 4; j++)
                acc[i][j] += qw[i] * kk[j] + qr[i] * rk[3 + j - i];
    }

    size_t base = (size_t)bn * QLEN * QLEN;
#pragma unroll
    for (int i = 0; i < 4; i++) {
        int gi = i0 + ii0 + i;
#pragma unroll
        for (int j = 0; j < 4; j++) {
            int gj = j0 + jj0 + j;
            float v = (gj <= gi) ? acc[i][j] * 0.125f : NEGINF;
            g_score[base + (size_t)gi * QLEN + gj] = v;
        }
    }
}

// ---------------- causal softmax -> split bf16 prob ----------------
__global__ __launch_bounds__(256) void softmax_kernel()
{
    int row = blockIdx.x;
    int i = row & 1023;
    const float* p = g_score + (size_t)row * QLEN;
    __nv_bfloat16* o = g_probbf + (size_t)row * 2048;
    int klen = i + 1;
    int tid = threadIdx.x;

    __shared__ float red[256];

    float mx = NEGINF;
    for (int j = tid; j < klen; j += 256) mx = fmaxf(mx, p[j]);
    red[tid] = mx;
    __syncthreads();
    for (int s = 128; s > 0; s >>= 1) {
        if (tid < s) red[tid] = fmaxf(red[tid], red[tid + s]);
        __syncthreads();
    }
    mx = red[0];
    __syncthreads();

    float sum = 0.f;
    for (int j = tid; j < klen; j += 256) sum += __expf(p[j] - mx);
    red[tid] = sum;
    __syncthreads();
    for (int s = 128; s > 0; s >>= 1) {
        if (tid < s) red[tid] += red[tid + s];
        __syncthreads();
    }
    float inv = 1.f / red[0];

    for (int j = tid; j < klen; j += 256) {
        float v = __expf(p[j] - mx) * inv;
        __nv_bfloat16 h, l;
        split2(v, h, l);
        o[j] = h;
        o[1024 + j] = l;
    }
    for (int j = klen + tid; j < QLEN; j += 256) {
        o[j] = __float2bfloat16(0.f);
        o[1024 + j] = __float2bfloat16(0.f);
    }
}

// ---------------- residual + layernorm ----------------
__global__ __launch_bounds__(256) void ln_kernel(
    const float* __restrict__ w, const float* __restrict__ gamma,
    const float* __restrict__ beta, float* __restrict__ out)
{
    int row = blockIdx.x;
    const float* wr = w + (size_t)row * DM;
    const float* ar = g_attn + (size_t)row * DM;
    int tid = threadIdx.x;

    float x[4];
    float s = 0.f, s2 = 0.f;
#pragma unroll
    for (int u = 0; u < 4; u++) {
        int c = tid + u * 256;
        x[u] = wr[c] + ar[c];
        s += x[u];
        s2 += x[u] * x[u];
    }
    __shared__ float rs[256], rs2[256];
    rs[tid] = s; rs2[tid] = s2;
    __syncthreads();
    for (int t = 128; t > 0; t >>= 1) {
        if (tid < t) { rs[tid] += rs[tid + t]; rs2[tid] += rs2[tid + t]; }
        __syncthreads();
    }
    float mu = rs[0] * (1.f / DM);
    float var = rs2[0] * (1.f / DM) - mu * mu;
    float rstd = rsqrtf(var + 1e-5f);
#pragma unroll
    for (int u = 0; u < 4; u++) {
        int c = tid + u * 256;
        out[(size_t)row * DM + c] = (x[u] - mu) * rstd * gamma[c] + beta[c];
    }
}

// ---------------- launch ----------------
extern "C" void kernel_launch(void* const* d_in, const int* in_sizes, int n_in,
                              void* d_out, int out_size)
{
    const float* w     = (const float*)d_in[0];
    const float* r     = (const float*)d_in[1];
    const float* rwb   = (const float*)d_in[2];
    const float* rrb   = (const float*)d_in[3];
    const float* W_qkv = (const float*)d_in[5];
    const float* W_r   = (const float*)d_in[6];
    const float* W_o   = (const float*)d_in[7];
    const float* gamma = (const float*)d_in[8];
    const float* beta  = (const float*)d_in[9];
    float* out = (float*)d_out;

    float *p_heads, *p_rk, *p_attn, *p_pv;
    __nv_bfloat16 *p_wbf, *p_rbf, *p_qkvt, *p_wrt, *p_wot, *p_vtbf, *p_probbf, *p_vecbf;
    cudaGetSymbolAddress((void**)&p_heads, g_heads);
    cudaGetSymbolAddress((void**)&p_rk, g_rk);
    cudaGetSymbolAddress((void**)&p_attn, g_attn);
    cudaGetSymbolAddress((void**)&p_wbf, g_wbf);
    cudaGetSymbolAddress((void**)&p_rbf, g_rbf);
    cudaGetSymbolAddress((void**)&p_qkvt, g_qkvt);
    cudaGetSymbolAddress((void**)&p_wrt, g_wrt);
    cudaGetSymbolAddress((void**)&p_wot, g_wot);
    cudaGetSymbolAddress((void**)&p_vtbf, g_vtbf);
    cudaGetSymbolAddress((void**)&p_probbf, g_probbf);
    cudaGetSymbolAddress((void**)&p_vecbf, g_vecbf);
    cudaGetSymbolAddress((void**)&p_pv, g_pv);

    static int attr_set = 0;
    if (!attr_set) {
        cudaFuncSetAttribute(score_kernel, cudaFuncAttributeMaxDynamicSharedMemorySize, 81920);
        cudaFuncSetAttribute(mma_gemm<128, 128>, cudaFuncAttributeMaxDynamicSharedMemorySize, 65536);
        cudaFuncSetAttribute(mma_gemm<128, 64>, cudaFuncAttributeMaxDynamicSharedMemorySize, 49152);
        attr_set = 1;
    }

    // 0) splits / transposes of inputs
    split_kernel<<<4096 * 1024 / 256, 256>>>(w, p_wbf, 1024);
    split_kernel<<<1024 * 1024 / 256, 256>>>(r, p_rbf, 1024);
    tsplit_kernel<<<dim3(16, 48), 256>>>(W_qkv, p_qkvt, 3072, 1024);
    tsplit_kernel<<<dim3(16, 16), 256>>>(W_r, p_wrt, 1024, 1024);
    tsplit_kernel<<<dim3(16, 16), 256>>>(W_o, p_wot, 1024, 1024);

    // 1) heads = w @ W_qkv  (HMMA, 4096x3072, K=1024)
    mma_gemm<128, 128><<<dim3(24, 32, 1), 256, 65536>>>(
        p_wbf, p_qkvt, p_heads, 1024, 2048, 2048, 3072, 0, 0, 0);

    // 2) r_k = r @ W_r  (HMMA, 1024x1024)
    mma_gemm<128, 128><<<dim3(8, 8, 1), 256, 65536>>>(
        p_rbf, p_wrt, p_rk, 1024, 2048, 2048, 1024, 0, 0, 0);

    // 3) packs
    pack_q_kernel<<<BN_TOT * QLEN * DH / 256, 256>>>(rwb, rrb);
    pack_kt_kernel<<<BN_TOT * QLEN * DH / 256, 256>>>();
    pack_vt_kernel<<<dim3(16, 64), 256>>>();
    pack_rk_kernel<<<NH * DH * QLEN / 256, 256>>>();

    // 4) fused scores (fp32, causal tiles only)
    score_kernel<<<dim3(16, 16, BN_TOT), 256, 81920>>>();

    // 5) softmax -> split bf16 prob
    softmax_kernel<<<BN_TOT * QLEN, 256>>>();

    // 6) vec = prob @ V  (HMMA, batched 64x: 1024x64, K=1024)
    mma_gemm<128, 64><<<dim3(1, 8, 64), 256, 49152>>>(
        p_probbf, p_vtbf, p_pv, 1024, 2048, 2048, 64,
        (long long)QLEN * 2048, (long long)DH * 2048, (long long)QLEN * DH);

    // 7) vec split to bf16 [4096][2048]
    vec_split_kernel<<<BN_TOT * QLEN * DH / 256, 256>>>();

    // 8) attn = vec @ W_o  (HMMA, 4096x1024)
    mma_gemm<128, 128><<<dim3(8, 32, 1), 256, 65536>>>(
        p_vecbf, p_wot, p_attn, 1024, 2048, 2048, 1024, 0, 0, 0);

    // 9) out = layernorm(w + attn)
    ln_kernel<<<4096, 256>>>(w, gamma, beta, out);
}

// round 4
// speedup vs baseline: 2.3236x; 1.4640x over previous
#include <cuda_runtime.h>
#include <cuda_bf16.h>
#include <cstdint>
#include <cstddef>

#define QLEN 1024
#define BSZ 4
#define DM 1024
#define NH 16
#define DH 64
#define BN_TOT 64
#define NEGINF -1e30f
#define KDIM 1024

__device__ __forceinline__ uint32_t smem_to_u32(const void* p) {
    uint32_t a;
    asm("{ .reg .u64 t; cvta.to.shared.u64 t, %1; cvt.u32.u64 %0, t; }" : "=r"(a) : "l"(p));
    return a;
}
#define SWZ128(b) ((b) ^ (((b) >> 3) & 0x70))

__device__ __forceinline__ void ldm_x4(uint32_t r[4], uint32_t addr) {
    asm volatile("ldmatrix.sync.aligned.m8n8.x4.shared.b16 {%0,%1,%2,%3}, [%4];"
                 : "=r"(r[0]), "=r"(r[1]), "=r"(r[2]), "=r"(r[3]) : "r"(addr));
}
__device__ __forceinline__ void mma16816(float c[4], const uint32_t a[4], const uint32_t b[2]) {
    asm volatile("mma.sync.aligned.m16n8k16.row.col.f32.bf16.bf16.f32 "
                 "{%0,%1,%2,%3}, {%4,%5,%6,%7}, {%8,%9}, {%0,%1,%2,%3};"
                 : "+f"(c[0]), "+f"(c[1]), "+f"(c[2]), "+f"(c[3])
                 : "r"(a[0]), "r"(a[1]), "r"(a[2]), "r"(a[3]), "r"(b[0]), "r"(b[1]));
}

// ---------------- scratch ----------------
__device__ float g_heads[(size_t)QLEN * BSZ * 3 * DM];
__device__ float g_rk[(size_t)QLEN * DM];
__device__ float g_AC[(size_t)BN_TOT * QLEN * QLEN];
__device__ float g_BD[(size_t)BN_TOT * QLEN * QLEN];
__device__ float g_pv[(size_t)BN_TOT * QLEN * DH];
__device__ float g_attn[(size_t)QLEN * BSZ * DM];
__device__ __nv_bfloat16 g_wbf[(size_t)QLEN * BSZ * 2 * KDIM];
__device__ __nv_bfloat16 g_rbf[(size_t)QLEN * 2 * KDIM];
__device__ __nv_bfloat16 g_qkvt[(size_t)3 * DM * 2 * KDIM];
__device__ __nv_bfloat16 g_wrt[(size_t)DM * 2 * KDIM];
__device__ __nv_bfloat16 g_wot[(size_t)DM * 2 * KDIM];
__device__ __nv_bfloat16 g_qwbf[(size_t)BN_TOT * QLEN * 2 * DH];   // [bn][i][hi64|lo64]
__device__ __nv_bfloat16 g_qrbf[(size_t)BN_TOT * QLEN * 2 * DH];
__device__ __nv_bfloat16 g_kbf[(size_t)BN_TOT * QLEN * 2 * DH];
__device__ __nv_bfloat16 g_rkbf[(size_t)NH * QLEN * 2 * DH];       // [n][m][hi64|lo64]
__device__ __nv_bfloat16 g_vtbf[(size_t)BN_TOT * DH * 2 * QLEN];
__device__ __nv_bfloat16 g_probbf[(size_t)BN_TOT * QLEN * 2 * QLEN];
__device__ __nv_bfloat16 g_vecbf[(size_t)QLEN * BSZ * 2 * KDIM];

__device__ __forceinline__ void split2(float x, __nv_bfloat16& h, __nv_bfloat16& l) {
    h = __float2bfloat16(x);
    l = __float2bfloat16(x - __bfloat162float(h));
}

// ---------------- HMMA GEMM: C[M,N] = A[M,2K] x Bt[N,2K] (3-term hi/lo) ----------------
// mode 0: full grid (blockIdx.x = n-tile, blockIdx.y = m-tile)
// mode 1: lower-tri 8x8 (blockIdx.x linear, jt<=it)       [AC tiles]
// mode 2: anti-tri 8x8 (blockIdx.x linear, it+mt>=7)      [BD tiles]
// causal!=0: limit K-tiles to (m0+BM)/64                  [PV]
// B batch index = blockIdx.z & bmask
template <int BM, int BN>
__global__ __launch_bounds__(256) void mma_gemm(
    const __nv_bfloat16* __restrict__ A, const __nv_bfloat16* __restrict__ Bt,
    float* __restrict__ C, int K, int lda, int ldb, int ldc,
    long long sA, long long sB, long long sC, int mode, int bmask, int causal)
{
    extern __shared__ char smem[];
    const uint32_t smem_u32 = smem_to_u32(smem);
    constexpr int ASZ = BM * 128;
    constexpr int BSZ_ = BN * 128;
    constexpr int A_OFF = 0;
    constexpr int B_OFF = 2 * ASZ;
    constexpr int ACH = BM / 32;
    constexpr int BCH = BN / 32;
    constexpr int WN = BN / 2;
    constexpr int MT = 2;
    constexpr int NT = WN / 8;

    const int tid = threadIdx.x;
    const int lane = tid & 31, warp = tid >> 5;
    const int wm = warp & 3, wn = warp >> 2;
    const int bz = blockIdx.z;

    int m0, n0;
    if (mode == 0) {
        m0 = blockIdx.y * BM;
        n0 = blockIdx.x * BN;
    } else {
        int x = blockIdx.x;
        int it = (int)floorf((sqrtf(8.f * x + 1.f) - 1.f) * 0.5f);
        while ((it + 1) * (it + 2) / 2 <= x) ++it;
        while (it * (it + 1) / 2 > x) --it;
        int jt = x - it * (it + 1) / 2;
        m0 = it * BM;
        n0 = (mode == 1 ? jt : 7 - jt) * BN;
    }

    const __nv_bfloat16* Ab = A + (size_t)bz * sA;
    const __nv_bfloat16* Bb = Bt + (size_t)(bz & bmask) * sB;
    float* Cb = C + (size_t)bz * sC;

    int KT = K / 64;
    if (causal) { int ke = (m0 + BM) >> 6; if (ke < KT) KT = ke; }
    const int T = 3 * KT;

    uint4 ra[ACH], rb[BCH];
    auto ldg_tile = [&](int t) {
        int p = t / KT, kt = t - p * KT;
        int aoff = ((p == 1) ? K : 0) + kt * 64;
        int boff = ((p == 2) ? K : 0) + kt * 64;
#pragma unroll
        for (int i = 0; i < ACH; i++) {
            int c = tid + i * 256, row = c >> 3, q = c & 7;
            ra[i] = *(const uint4*)(Ab + (size_t)(m0 + row) * lda + aoff + q * 8);
        }
#pragma unroll
        for (int i = 0; i < BCH; i++) {
            int c = tid + i * 256, row = c >> 3, q = c & 7;
            rb[i] = *(const uint4*)(Bb + (size_t)(n0 + row) * ldb + boff + q * 8);
        }
    };
    auto sts_tile = [&](int s) {
#pragma unroll
        for (int i = 0; i < ACH; i++) {
            int c = tid + i * 256, row = c >> 3, q = c & 7;
            int b = SWZ128(row * 128 + q * 16);
            *(uint4*)(smem + A_OFF + s * ASZ + b) = ra[i];
        }
#pragma unroll
        for (int i = 0; i < BCH; i++) {
            int c = tid + i * 256, row = c >> 3, q = c & 7;
            int b = SWZ128(row * 128 + q * 16);
            *(uint4*)(smem + B_OFF + s * BSZ_ + b) = rb[i];
        }
    };

    float acc[MT][NT][4];
#pragma unroll
    for (int mt = 0; mt < MT; mt++)
#pragma unroll
        for (int nt = 0; nt < NT; nt++)
#pragma unroll
            for (int u = 0; u < 4; u++) acc[mt][nt][u] = 0.f;

    ldg_tile(0);
    sts_tile(0);
    __syncthreads();

    for (int t = 0; t < T; t++) {
        const int s = t & 1;
        const bool more = (t + 1 < T);
        if (more) ldg_tile(t + 1);

        const uint32_t abase = smem_u32 + A_OFF + s * ASZ;
        const uint32_t bbase = smem_u32 + B_OFF + s * BSZ_;
#pragma unroll
        for (int kk = 0; kk < 4; kk++) {
            const int seg = kk * 32 + (lane >> 4) * 16;
            uint32_t af[MT][4], bf[NT][2];
#pragma unroll
            for (int mt = 0; mt < MT; mt++) {
                int row = wm * 32 + mt * 16 + (lane & 15);
                ldm_x4(af[mt], abase + SWZ128(row * 128 + seg));
            }
#pragma unroll
            for (int p = 0; p < NT / 2; p++) {
                int row = wn * WN + p * 16 + (lane & 15);
                uint32_t r[4];
                ldm_x4(r, bbase + SWZ128(row * 128 + seg));
                bf[2 * p][0] = r[0]; bf[2 * p][1] = r[2];
                bf[2 * p + 1][0] = r[1]; bf[2 * p + 1][1] = r[3];
            }
#pragma unroll
            for (int mt = 0; mt < MT; mt++)
#pragma unroll
                for (int nt = 0; nt < NT; nt++)
                    mma16816(acc[mt][nt], af[mt], bf[nt]);
        }
        __syncthreads();
        if (more) {
            sts_tile((t + 1) & 1);
            __syncthreads();
        }
    }

#pragma unroll
    for (int mt = 0; mt < MT; mt++) {
#pragma unroll
        for (int nt = 0; nt < NT; nt++) {
            int mrow = m0 + wm * 32 + mt * 16 + (lane >> 2);
            int col = n0 + wn * WN + nt * 8 + (lane & 3) * 2;
            *(float2*)&Cb[(size_t)mrow * ldc + col] = make_float2(acc[mt][nt][0], acc[mt][nt][1]);
            *(float2*)&Cb[(size_t)(mrow + 8) * ldc + col] = make_float2(acc[mt][nt][2], acc[mt][nt][3]);
        }
    }
}

// ---------------- split / transpose kernels ----------------
__global__ void split_kernel(const float* __restrict__ X, __nv_bfloat16* __restrict__ Y, int cols)
{
    int idx = blockIdx.x * 256 + threadIdx.x;
    int row = idx / cols, col = idx - row * cols;
    __nv_bfloat16 h, l;
    split2(X[idx], h, l);
    Y[(size_t)row * 2 * cols + col] = h;
    Y[(size_t)row * 2 * cols + cols + col] = l;
}

__global__ __launch_bounds__(256) void tsplit_kernel(const float* __restrict__ X,
                                                     __nv_bfloat16* __restrict__ Y, int N, int K)
{
    __shared__ float sm[64][65];
    int k0 = blockIdx.x * 64, n0 = blockIdx.y * 64;
    int tid = threadIdx.x;
    for (int e = tid; e < 4096; e += 256) {
        int r = e >> 6, c = e & 63;
        sm[c][r] = X[(size_t)(k0 + r) * N + n0 + c];
    }
    __syncthreads();
    for (int e = tid; e < 4096; e += 256) {
        int r = e >> 6, c = e & 63;
        __nv_bfloat16 h, l;
        split2(sm[r][c], h, l);
        Y[(size_t)(n0 + r) * 2 * K + k0 + c] = h;
        Y[(size_t)(n0 + r) * 2 * K + K + k0 + c] = l;
    }
}

// heads -> qw/qr/k split bf16 [bn][i][hi64|lo64]
__global__ void pack_qk_kernel(const float* __restrict__ rwb, const float* __restrict__ rrb)
{
    int idx = blockIdx.x * 256 + threadIdx.x;      // (bn, i, d)
    int d = idx & 63, i = (idx >> 6) & 1023, bn = idx >> 16;
    int b = bn >> 4, n = bn & 15;
    size_t hbase = (size_t)(i * 4 + b) * 3072 + n * 64 + d;
    float q = g_heads[hbase];
    float k = g_heads[hbase + 1024];
    size_t o = ((size_t)bn * QLEN + i) * 128 + d;
    __nv_bfloat16 h, l;
    split2(q + rwb[n * 64 + d], h, l);
    g_qwbf[o] = h; g_qwbf[o + 64] = l;
    split2(q + rrb[n * 64 + d], h, l);
    g_qrbf[o] = h; g_qrbf[o + 64] = l;
    split2(k, h, l);
    g_kbf[o] = h; g_kbf[o + 64] = l;
}

__global__ void pack_rk_kernel()
{
    int idx = blockIdx.x * 256 + threadIdx.x;      // (n, m, d)
    int d = idx & 63, m = (idx >> 6) & 1023, n = idx >> 16;
    __nv_bfloat16 h, l;
    split2(g_rk[(size_t)m * 1024 + n * 64 + d], h, l);
    size_t o = ((size_t)n * QLEN + m) * 128 + d;
    g_rkbf[o] = h; g_rkbf[o + 64] = l;
}

__global__ __launch_bounds__(256) void pack_vt_kernel()
{
    __shared__ float sm[64][65];
    int bn = blockIdx.y, b = bn >> 4, n = bn & 15;
    int j0 = blockIdx.x * 64;
    int tid = threadIdx.x;
    for (int e = tid; e < 4096; e += 256) {
        int jj = e >> 6, d = e & 63;
        sm[d][jj] = g_heads[(size_t)((j0 + jj) * 4 + b) * 3072 + 2048 + n * 64 + d];
    }
    __syncthreads();
    for (int e = tid; e < 4096; e += 256) {
        int d = e >> 6, jj = e & 63;
        __nv_bfloat16 h, l;
        split2(sm[d][jj], h, l);
        g_vtbf[((size_t)bn * 64 + d) * 2048 + j0 + jj] = h;
        g_vtbf[((size_t)bn * 64 + d) * 2048 + 1024 + j0 + jj] = l;
    }
}

__global__ void vec_split_kernel()
{
    int idx = blockIdx.x * 256 + threadIdx.x;
    int d = idx & 63, i = (idx >> 6) & 1023, bn = idx >> 16;
    int b = bn >> 4, n = bn & 15;
    __nv_bfloat16 h, l;
    split2(g_pv[idx], h, l);
    size_t row = (size_t)(i * 4 + b) * 2048;
    g_vecbf[row + n * 64 + d] = h;
    g_vecbf[row + 1024 + n * 64 + d] = l;
}

// ---------------- fused shift + add + scale + softmax -> split bf16 prob ----------------
__global__ __launch_bounds__(256) void sm_softmax_kernel()
{
    int row = blockIdx.x;                // bn*1024 + i
    int i = row & 1023;
    const float* ac = g_AC + (size_t)row * QLEN;
    const float* bd = g_BD + (size_t)row * QLEN + (1023 - i);
    __nv_bfloat16* o = g_probbf + (size_t)row * 2048;
    int klen = i + 1;
    int tid = threadIdx.x;

    float s[4];
    float mx = NEGINF;
#pragma unroll
    for (int u = 0; u < 4; u++) {
        int j = tid + u * 256;
        s[u] = (j < klen) ? (ac[j] + bd[j]) * 0.125f : NEGINF;
        mx = fmaxf(mx, s[u]);
    }

    __shared__ float red[256];
    red[tid] = mx;
    __syncthreads();
    for (int t = 128; t > 0; t >>= 1) {
        if (tid < t) red[tid] = fmaxf(red[tid], red[tid + t]);
        __syncthreads();
    }
    mx = red[0];
    __syncthreads();

    float e[4], sum = 0.f;
#pragma unroll
    for (int u = 0; u < 4; u++) {
        e[u] = __expf(s[u] - mx);        // exp(NEGINF - mx) = 0
        sum += e[u];
    }
    red[tid] = sum;
    __syncthreads();
    for (int t = 128; t > 0; t >>= 1) {
        if (tid < t) red[tid] += red[tid + t];
        __syncthreads();
    }
    float inv = 1.f / red[0];

    int jmax = ((i >> 7) + 1) << 7;      // PV only reads K up to tile end
#pragma unroll
    for (int u = 0; u < 4; u++) {
        int j = tid + u * 256;
        if (j < klen) {
            __nv_bfloat16 h, l;
            split2(e[u] * inv, h, l);
            o[j] = h;
            o[1024 + j] = l;
        } else if (j < jmax) {
            o[j] = __float2bfloat16(0.f);
            o[1024 + j] = __float2bfloat16(0.f);
        }
    }
}

// ---------------- residual + layernorm ----------------
__global__ __launch_bounds__(256) void ln_kernel(
    const float* __restrict__ w, const float* __restrict__ gamma,
    const float* __restrict__ beta, float* __restrict__ out)
{
    int row = blockIdx.x;
    const float* wr = w + (size_t)row * DM;
    const float* ar = g_attn + (size_t)row * DM;
    int tid = threadIdx.x;

    float x[4];
    float s = 0.f, s2 = 0.f;
#pragma unroll
    for (int u = 0; u < 4; u++) {
        int c = tid + u * 256;
        x[u] = wr[c] + ar[c];
        s += x[u];
        s2 += x[u] * x[u];
    }
    __shared__ float rs[256], rs2[256];
    rs[tid] = s; rs2[tid] = s2;
    __syncthreads();
    for (int t = 128; t > 0; t >>= 1) {
        if (tid < t) { rs[tid] += rs[tid + t]; rs2[tid] += rs2[tid + t]; }
        __syncthreads();
    }
    float mu = rs[0] * (1.f / DM);
    float var = rs2[0] * (1.f / DM) - mu * mu;
    float rstd = rsqrtf(var + 1e-5f);
#pragma unroll
    for (int u = 0; u < 4; u++) {
        int c = tid + u * 256;
        out[(size_t)row * DM + c] = (x[u] - mu) * rstd * gamma[c] + beta[c];
    }
}

// ---------------- launch ----------------
extern "C" void kernel_launch(void* const* d_in, const int* in_sizes, int n_in,
                              void* d_out, int out_size)
{
    const float* w     = (const float*)d_in[0];
    const float* r     = (const float*)d_in[1];
    const float* rwb   = (const float*)d_in[2];
    const float* rrb   = (const float*)d_in[3];
    const float* W_qkv = (const float*)d_in[5];
    const float* W_r   = (const float*)d_in[6];
    const float* W_o   = (const float*)d_in[7];
    const float* gamma = (const float*)d_in[8];
    const float* beta  = (const float*)d_in[9];
    float* out = (float*)d_out;

    float *p_heads, *p_rk, *p_AC, *p_BD, *p_pv, *p_attn;
    __nv_bfloat16 *p_wbf, *p_rbf, *p_qkvt, *p_wrt, *p_wot;
    __nv_bfloat16 *p_qwbf, *p_qrbf, *p_kbf, *p_rkbf, *p_vtbf, *p_probbf, *p_vecbf;
    cudaGetSymbolAddress((void**)&p_heads, g_heads);
    cudaGetSymbolAddress((void**)&p_rk, g_rk);
    cudaGetSymbolAddress((void**)&p_AC, g_AC);
    cudaGetSymbolAddress((void**)&p_BD, g_BD);
    cudaGetSymbolAddress((void**)&p_pv, g_pv);
    cudaGetSymbolAddress((void**)&p_attn, g_attn);
    cudaGetSymbolAddress((void**)&p_wbf, g_wbf);
    cudaGetSymbolAddress((void**)&p_rbf, g_rbf);
    cudaGetSymbolAddress((void**)&p_qkvt, g_qkvt);
    cudaGetSymbolAddress((void**)&p_wrt, g_wrt);
    cudaGetSymbolAddress((void**)&p_wot, g_wot);
    cudaGetSymbolAddress((void**)&p_qwbf, g_qwbf);
    cudaGetSymbolAddress((void**)&p_qrbf, g_qrbf);
    cudaGetSymbolAddress((void**)&p_kbf, g_kbf);
    cudaGetSymbolAddress((void**)&p_rkbf, g_rkbf);
    cudaGetSymbolAddress((void**)&p_vtbf, g_vtbf);
    cudaGetSymbolAddress((void**)&p_probbf, g_probbf);
    cudaGetSymbolAddress((void**)&p_vecbf, g_vecbf);

    cudaFuncSetAttribute(mma_gemm<128, 128>, cudaFuncAttributeMaxDynamicSharedMemorySize, 65536);
    cudaFuncSetAttribute(mma_gemm<128, 64>, cudaFuncAttributeMaxDynamicSharedMemorySize, 49152);

    const int FULLMASK = 0x7FFFFFFF;

    // 0) splits / transposes of inputs
    split_kernel<<<4096 * 1024 / 256, 256>>>(w, p_wbf, 1024);
    split_kernel<<<1024 * 1024 / 256, 256>>>(r, p_rbf, 1024);
    tsplit_kernel<<<dim3(16, 48), 256>>>(W_qkv, p_qkvt, 3072, 1024);
    tsplit_kernel<<<dim3(16, 16), 256>>>(W_r, p_wrt, 1024, 1024);
    tsplit_kernel<<<dim3(16, 16), 256>>>(W_o, p_wot, 1024, 1024);

    // 1) heads = w @ W_qkv
    mma_gemm<128, 128><<<dim3(24, 32, 1), 256, 65536>>>(
        p_wbf, p_qkvt, p_heads, 1024, 2048, 2048, 3072, 0, 0, 0, 0, FULLMASK, 0);

    // 2) r_k = r @ W_r
    mma_gemm<128, 128><<<dim3(8, 8, 1), 256, 65536>>>(
        p_rbf, p_wrt, p_rk, 1024, 2048, 2048, 1024, 0, 0, 0, 0, FULLMASK, 0);

    // 3) packs (bf16 hi/lo)
    pack_qk_kernel<<<BN_TOT * QLEN * DH / 256, 256>>>(rwb, rrb);
    pack_rk_kernel<<<NH * QLEN * DH / 256, 256>>>();
    pack_vt_kernel<<<dim3(16, 64), 256>>>();

    // 4) AC = qw @ k^T   (batched 64, lower-tri tiles only, K=64)
    mma_gemm<128, 128><<<dim3(36, 1, BN_TOT), 256, 65536>>>(
        p_qwbf, p_kbf, p_AC, 64, 128, 128, 1024,
        (long long)QLEN * 128, (long long)QLEN * 128, (long long)QLEN * QLEN,
        1, FULLMASK, 0);

    // 5) BDrel = qr @ rk^T  (batched 64, B batch = head = bn&15, anti-tri tiles)
    mma_gemm<128, 128><<<dim3(36, 1, BN_TOT), 256, 65536>>>(
        p_qrbf, p_rkbf, p_BD, 64, 128, 128, 1024,
        (long long)QLEN * 128, (long long)QLEN * 128, (long long)QLEN * QLEN,
        2, 15, 0);

    // 6) fused shift+add+softmax -> split bf16 prob
    sm_softmax_kernel<<<BN_TOT * QLEN, 256>>>();

    // 7) vec = prob @ V  (batched 64, causal K-limit)
    mma_gemm<128, 64><<<dim3(1, 8, BN_TOT), 256, 49152>>>(
        p_probbf, p_vtbf, p_pv, 1024, 2048, 2048, 64,
        (long long)QLEN * 2048, (long long)DH * 2048, (long long)QLEN * DH,
        0, FULLMASK, 1);

    // 8) vec split
    vec_split_kernel<<<BN_TOT * QLEN * DH / 256, 256>>>();

    // 9) attn = vec @ W_o
    mma_gemm<128, 128><<<dim3(8, 32, 1), 256, 65536>>>(
        p_vecbf, p_wot, p_attn, 1024, 2048, 2048, 1024, 0, 0, 0, 0, FULLMASK, 0);

    // 10) out = layernorm(w + attn)
    ln_kernel<<<4096, 256>>>(w, gamma, beta, out);
}

// round 5
// speedup vs baseline: 2.9115x; 1.2530x over previous
#include <cuda_runtime.h>
#include <cuda_bf16.h>
#include <cstdint>
#include <cstddef>

#define QLEN 1024
#define BSZ 4
#define DM 1024
#define NH 16
#define DH 64
#define BN_TOT 64
#define NEGINF -1e30f
#define KDIM 1024

__device__ __forceinline__ uint32_t smem_to_u32(const void* p) {
    uint32_t a;
    asm("{ .reg .u64 t; cvta.to.shared.u64 t, %1; cvt.u32.u64 %0, t; }" : "=r"(a) : "l"(p));
    return a;
}
#define SWZ128(b) ((b) ^ (((b) >> 3) & 0x70))

__device__ __forceinline__ void ldm_x4(uint32_t r[4], uint32_t addr) {
    asm volatile("ldmatrix.sync.aligned.m8n8.x4.shared.b16 {%0,%1,%2,%3}, [%4];"
                 : "=r"(r[0]), "=r"(r[1]), "=r"(r[2]), "=r"(r[3]) : "r"(addr));
}
__device__ __forceinline__ void mma16816(float c[4], const uint32_t a[4], const uint32_t b[2]) {
    asm volatile("mma.sync.aligned.m16n8k16.row.col.f32.bf16.bf16.f32 "
                 "{%0,%1,%2,%3}, {%4,%5,%6,%7}, {%8,%9}, {%0,%1,%2,%3};"
                 : "+f"(c[0]), "+f"(c[1]), "+f"(c[2]), "+f"(c[3])
                 : "r"(a[0]), "r"(a[1]), "r"(a[2]), "r"(a[3]), "r"(b[0]), "r"(b[1]));
}
__device__ __forceinline__ void cp_async16(uint32_t saddr, const void* gptr) {
    asm volatile("cp.async.cg.shared.global [%0], [%1], 16;" :: "r"(saddr), "l"(gptr));
}
__device__ __forceinline__ void cp_commit() { asm volatile("cp.async.commit_group;"); }
template <int N>
__device__ __forceinline__ void cp_wait() { asm volatile("cp.async.wait_group %0;" :: "n"(N)); }

// ---------------- scratch ----------------
__device__ float g_heads[(size_t)QLEN * BSZ * 3 * DM];
__device__ float g_rk[(size_t)QLEN * DM];
__device__ float g_AC[(size_t)BN_TOT * QLEN * QLEN];
__device__ float g_BD[(size_t)BN_TOT * QLEN * QLEN];
__device__ float g_attn[(size_t)QLEN * BSZ * DM];
__device__ __nv_bfloat16 g_wbf[(size_t)QLEN * BSZ * 2 * KDIM];
__device__ __nv_bfloat16 g_rbf[(size_t)QLEN * 2 * KDIM];
__device__ __nv_bfloat16 g_qkvt[(size_t)3 * DM * 2 * KDIM];
__device__ __nv_bfloat16 g_wrt[(size_t)DM * 2 * KDIM];
__device__ __nv_bfloat16 g_wot[(size_t)DM * 2 * KDIM];
__device__ __nv_bfloat16 g_qwbf[(size_t)BN_TOT * QLEN * 2 * DH];
__device__ __nv_bfloat16 g_qrbf[(size_t)BN_TOT * QLEN * 2 * DH];
__device__ __nv_bfloat16 g_kbf[(size_t)BN_TOT * QLEN * 2 * DH];
__device__ __nv_bfloat16 g_rkbf[(size_t)NH * QLEN * 2 * DH];
__device__ __nv_bfloat16 g_vtbf[(size_t)BN_TOT * DH * 2 * QLEN];
__device__ __nv_bfloat16 g_probbf[(size_t)BN_TOT * QLEN * 2 * QLEN];
__device__ __nv_bfloat16 g_vecbf[(size_t)QLEN * BSZ * 2 * KDIM];

__device__ __forceinline__ void split2(float x, __nv_bfloat16& h, __nv_bfloat16& l) {
    h = __float2bfloat16(x);
    l = __float2bfloat16(x - __bfloat162float(h));
}

// ---------------- HMMA GEMM v2: load-once, 3-pass hi/lo ----------------
// A[M][2K] = [hi(K) | lo(K)] per row; Bt[N][2K] likewise. C = A*Bt^T (3-term).
// mode 0: full grid; 1: lower-tri 8x8 (AC); 2: anti-tri 8x8 (BD)
// causal: limit K-tiles to (m0+BM)/64
// EPI 0: fp32 C; EPI 1: split-bf16 into g_vecbf (PV)
template <int BM, int BN, int EPI>
__global__ __launch_bounds__(256) void mma_gemm2(
    const __nv_bfloat16* __restrict__ A, const __nv_bfloat16* __restrict__ Bt,
    float* __restrict__ C, int K, int lda, int ldb, int ldc,
    long long sA, long long sB, long long sC, int mode, int bmask, int causal)
{
    extern __shared__ char smem[];
    const uint32_t smem_u32 = smem_to_u32(smem);
    constexpr int AHB = BM * 128;                 // bytes of one A half (hi or lo)
    constexpr int BHB = BN * 128;
    constexpr int STG = 2 * AHB + 2 * BHB;        // stage: A_hi A_lo B_hi B_lo
    constexpr int WN = BN / 2;
    constexpr int MT = 2;
    constexpr int NT = WN / 8;

    const int tid = threadIdx.x;
    const int lane = tid & 31, warp = tid >> 5;
    const int wm = warp & 3, wn = warp >> 2;
    const int bz = blockIdx.z;

    int m0, n0;
    if (mode == 0) {
        m0 = blockIdx.y * BM;
        n0 = blockIdx.x * BN;
    } else {
        int x = blockIdx.x;
        int it = (int)floorf((sqrtf(8.f * x + 1.f) - 1.f) * 0.5f);
        while ((it + 1) * (it + 2) / 2 <= x) ++it;
        while (it * (it + 1) / 2 > x) --it;
        int jt = x - it * (it + 1) / 2;
        m0 = it * BM;
        n0 = (mode == 1 ? jt : 7 - jt) * BN;
    }

    const __nv_bfloat16* Ab = A + (size_t)bz * sA;
    const __nv_bfloat16* Bb = Bt + (size_t)(bz & bmask) * sB;

    int KT = K / 64;
    if (causal) { int ke = (m0 + BM) >> 6; if (ke < KT) KT = ke; }

    // cp.async one stage (hi+lo of A and B) into buffer s
    auto cp_stage = [&](int kt, int s) {
        const uint32_t base = smem_u32 + s * STG;
#pragma unroll
        for (int i = 0; i < BM / 32; i++) {
            int c = tid + i * 256, row = c >> 3, q = c & 7;
            uint32_t sw = SWZ128(row * 128 + q * 16);
            const __nv_bfloat16* gp = Ab + (size_t)(m0 + row) * lda + kt * 64 + q * 8;
            cp_async16(base + sw, gp);                    // A hi
            cp_async16(base + AHB + sw, gp + K);          // A lo
        }
#pragma unroll
        for (int i = 0; i < BN / 32; i++) {
            int c = tid + i * 256, row = c >> 3, q = c & 7;
            uint32_t sw = SWZ128(row * 128 + q * 16);
            const __nv_bfloat16* gp = Bb + (size_t)(n0 + row) * ldb + kt * 64 + q * 8;
            cp_async16(base + 2 * AHB + sw, gp);          // B hi
            cp_async16(base + 2 * AHB + BHB + sw, gp + K);// B lo
        }
        cp_commit();
    };

    float acc[MT][NT][4];
#pragma unroll
    for (int mt = 0; mt < MT; mt++)
#pragma unroll
        for (int nt = 0; nt < NT; nt++)
#pragma unroll
            for (int u = 0; u < 4; u++) acc[mt][nt][u] = 0.f;

    cp_stage(0, 0);
    if (KT > 1) cp_stage(1, 1);

    for (int t = 0; t < KT; t++) {
        const int s = t & 1;
        if (t < KT - 1) cp_wait<1>(); else cp_wait<0>();
        __syncthreads();

        const uint32_t ah = smem_u32 + s * STG;
        const uint32_t al = ah + AHB;
        const uint32_t bh = ah + 2 * AHB;
        const uint32_t bl = bh + BHB;
#pragma unroll
        for (int kk = 0; kk < 4; kk++) {
            const int seg = kk * 32 + (lane >> 4) * 16;
            uint32_t afh[MT][4], afl[MT][4], bfh[NT][2], bfl[NT][2];
#pragma unroll
            for (int mt = 0; mt < MT; mt++) {
                int sw = SWZ128((wm * 32 + mt * 16 + (lane & 15)) * 128 + seg);
                ldm_x4(afh[mt], ah + sw);
                ldm_x4(afl[mt], al + sw);
            }
#pragma unroll
            for (int p = 0; p < NT / 2; p++) {
                int sw = SWZ128((wn * WN + p * 16 + (lane & 15)) * 128 + seg);
                uint32_t r[4];
                ldm_x4(r, bh + sw);
                bfh[2 * p][0] = r[0]; bfh[2 * p][1] = r[2];
                bfh[2 * p + 1][0] = r[1]; bfh[2 * p + 1][1] = r[3];
                ldm_x4(r, bl + sw);
                bfl[2 * p][0] = r[0]; bfl[2 * p][1] = r[2];
                bfl[2 * p + 1][0] = r[1]; bfl[2 * p + 1][1] = r[3];
            }
#pragma unroll
            for (int mt = 0; mt < MT; mt++)
#pragma unroll
                for (int nt = 0; nt < NT; nt++) {
                    mma16816(acc[mt][nt], afh[mt], bfh[nt]);
                    mma16816(acc[mt][nt], afl[mt], bfh[nt]);
                    mma16816(acc[mt][nt], afh[mt], bfl[nt]);
                }
        }
        __syncthreads();
        if (t + 2 < KT) cp_stage(t + 2, s);
    }

    if (EPI == 0) {
        float* Cb = C + (size_t)bz * sC;
#pragma unroll
        for (int mt = 0; mt < MT; mt++)
#pragma unroll
            for (int nt = 0; nt < NT; nt++) {
                int mrow = m0 + wm * 32 + mt * 16 + (lane >> 2);
                int col = n0 + wn * WN + nt * 8 + (lane & 3) * 2;
                *(float2*)&Cb[(size_t)mrow * ldc + col] = make_float2(acc[mt][nt][0], acc[mt][nt][1]);
                *(float2*)&Cb[(size_t)(mrow + 8) * ldc + col] = make_float2(acc[mt][nt][2], acc[mt][nt][3]);
            }
    } else {
        // PV epilogue: write split bf16 directly into g_vecbf [i*4+b][n*64+d | 1024+n*64+d]
        int b = bz >> 4, n = bz & 15;
#pragma unroll
        for (int mt = 0; mt < MT; mt++)
#pragma unroll
            for (int nt = 0; nt < NT; nt++) {
                int i0r = m0 + wm * 32 + mt * 16 + (lane >> 2);
                int d0 = n0 + wn * WN + nt * 8 + (lane & 3) * 2;
#pragma unroll
                for (int half = 0; half < 2; half++) {
                    int irow = i0r + half * 8;
                    size_t orow = (size_t)(irow * 4 + b) * 2048 + n * 64 + d0;
                    __nv_bfloat16 h0, l0, h1, l1;
                    split2(acc[mt][nt][2 * half + 0], h0, l0);
                    split2(acc[mt][nt][2 * half + 1], h1, l1);
                    *(__nv_bfloat162*)&g_vecbf[orow] = __nv_bfloat162(h0, h1);
                    *(__nv_bfloat162*)&g_vecbf[orow + 1024] = __nv_bfloat162(l0, l1);
                }
            }
    }
}

// ---------------- split / transpose kernels ----------------
__global__ void split_kernel(const float* __restrict__ X, __nv_bfloat16* __restrict__ Y, int cols)
{
    int idx = blockIdx.x * 256 + threadIdx.x;
    int row = idx / cols, col = idx - row * cols;
    __nv_bfloat16 h, l;
    split2(X[idx], h, l);
    Y[(size_t)row * 2 * cols + col] = h;
    Y[(size_t)row * 2 * cols + cols + col] = l;
}

__global__ __launch_bounds__(256) void tsplit_kernel(const float* __restrict__ X,
                                                     __nv_bfloat16* __restrict__ Y, int N, int K)
{
    __shared__ float sm[64][65];
    int k0 = blockIdx.x * 64, n0 = blockIdx.y * 64;
    int tid = threadIdx.x;
    for (int e = tid; e < 4096; e += 256) {
        int r = e >> 6, c = e & 63;
        sm[c][r] = X[(size_t)(k0 + r) * N + n0 + c];
    }
    __syncthreads();
    for (int e = tid; e < 4096; e += 256) {
        int r = e >> 6, c = e & 63;
        __nv_bfloat16 h, l;
        split2(sm[r][c], h, l);
        Y[(size_t)(n0 + r) * 2 * K + k0 + c] = h;
        Y[(size_t)(n0 + r) * 2 * K + K + k0 + c] = l;
    }
}

__global__ void pack_qk_kernel(const float* __restrict__ rwb, const float* __restrict__ rrb)
{
    int idx = blockIdx.x * 256 + threadIdx.x;
    int d = idx & 63, i = (idx >> 6) & 1023, bn = idx >> 16;
    int b = bn >> 4, n = bn & 15;
    size_t hbase = (size_t)(i * 4 + b) * 3072 + n * 64 + d;
    float q = g_heads[hbase];
    float k = g_heads[hbase + 1024];
    size_t o = ((size_t)bn * QLEN + i) * 128 + d;
    __nv_bfloat16 h, l;
    split2(q + rwb[n * 64 + d], h, l);
    g_qwbf[o] = h; g_qwbf[o + 64] = l;
    split2(q + rrb[n * 64 + d], h, l);
    g_qrbf[o] = h; g_qrbf[o + 64] = l;
    split2(k, h, l);
    g_kbf[o] = h; g_kbf[o + 64] = l;
}

__global__ void pack_rk_kernel()
{
    int idx = blockIdx.x * 256 + threadIdx.x;
    int d = idx & 63, m = (idx >> 6) & 1023, n = idx >> 16;
    __nv_bfloat16 h, l;
    split2(g_rk[(size_t)m * 1024 + n * 64 + d], h, l);
    size_t o = ((size_t)n * QLEN + m) * 128 + d;
    g_rkbf[o] = h; g_rkbf[o + 64] = l;
}

__global__ __launch_bounds__(256) void pack_vt_kernel()
{
    __shared__ float sm[64][65];
    int bn = blockIdx.y, b = bn >> 4, n = bn & 15;
    int j0 = blockIdx.x * 64;
    int tid = threadIdx.x;
    for (int e = tid; e < 4096; e += 256) {
        int jj = e >> 6, d = e & 63;
        sm[d][jj] = g_heads[(size_t)((j0 + jj) * 4 + b) * 3072 + 2048 + n * 64 + d];
    }
    __syncthreads();
    for (int e = tid; e < 4096; e += 256) {
        int d = e >> 6, jj = e & 63;
        __nv_bfloat16 h, l;
        split2(sm[d][jj], h, l);
        g_vtbf[((size_t)bn * 64 + d) * 2048 + j0 + jj] = h;
        g_vtbf[((size_t)bn * 64 + d) * 2048 + 1024 + j0 + jj] = l;
    }
}

// ---------------- fused shift + add + scale + softmax -> split bf16 prob ----------------
__global__ __launch_bounds__(256) void sm_softmax_kernel()
{
    int row = blockIdx.x;
    int i = row & 1023;
    const float* ac = g_AC + (size_t)row * QLEN;
    const float* bd = g_BD + (size_t)row * QLEN + (1023 - i);
    __nv_bfloat16* o = g_probbf + (size_t)row * 2048;
    int klen = i + 1;
    int tid = threadIdx.x;

    float s[4];
    float mx = NEGINF;
#pragma unroll
    for (int u = 0; u < 4; u++) {
        int j = tid + u * 256;
        s[u] = (j < klen) ? (ac[j] + bd[j]) * 0.125f : NEGINF;
        mx = fmaxf(mx, s[u]);
    }

    __shared__ float red[256];
    red[tid] = mx;
    __syncthreads();
    for (int t = 128; t > 0; t >>= 1) {
        if (tid < t) red[tid] = fmaxf(red[tid], red[tid + t]);
        __syncthreads();
    }
    mx = red[0];
    __syncthreads();

    float e[4], sum = 0.f;
#pragma unroll
    for (int u = 0; u < 4; u++) {
        e[u] = __expf(s[u] - mx);
        sum += e[u];
    }
    red[tid] = sum;
    __syncthreads();
    for (int t = 128; t > 0; t >>= 1) {
        if (tid < t) red[tid] += red[tid + t];
        __syncthreads();
    }
    float inv = 1.f / red[0];

    int jmax = ((i >> 7) + 1) << 7;
#pragma unroll
    for (int u = 0; u < 4; u++) {
        int j = tid + u * 256;
        if (j < klen) {
            __nv_bfloat16 h, l;
            split2(e[u] * inv, h, l);
            o[j] = h;
            o[1024 + j] = l;
        } else if (j < jmax) {
            o[j] = __float2bfloat16(0.f);
            o[1024 + j] = __float2bfloat16(0.f);
        }
    }
}

// ---------------- residual + layernorm ----------------
__global__ __launch_bounds__(256) void ln_kernel(
    const float* __restrict__ w, const float* __restrict__ gamma,
    const float* __restrict__ beta, float* __restrict__ out)
{
    int row = blockIdx.x;
    const float* wr = w + (size_t)row * DM;
    const float* ar = g_attn + (size_t)row * DM;
    int tid = threadIdx.x;

    float x[4];
    float s = 0.f, s2 = 0.f;
#pragma unroll
    for (int u = 0; u < 4; u++) {
        int c = tid + u * 256;
        x[u] = wr[c] + ar[c];
        s += x[u];
        s2 += x[u] * x[u];
    }
    __shared__ float rs[256], rs2[256];
    rs[tid] = s; rs2[tid] = s2;
    __syncthreads();
    for (int t = 128; t > 0; t >>= 1) {
        if (tid < t) { rs[tid] += rs[tid + t]; rs2[tid] += rs2[tid + t]; }
        __syncthreads();
    }
    float mu = rs[0] * (1.f / DM);
    float var = rs2[0] * (1.f / DM) - mu * mu;
    float rstd = rsqrtf(var + 1e-5f);
#pragma unroll
    for (int u = 0; u < 4; u++) {
        int c = tid + u * 256;
        out[(size_t)row * DM + c] = (x[u] - mu) * rstd * gamma[c] + beta[c];
    }
}

// ---------------- launch ----------------
extern "C" void kernel_launch(void* const* d_in, const int* in_sizes, int n_in,
                              void* d_out, int out_size)
{
    const float* w     = (const float*)d_in[0];
    const float* r     = (const float*)d_in[1];
    const float* rwb   = (const float*)d_in[2];
    const float* rrb   = (const float*)d_in[3];
    const float* W_qkv = (const float*)d_in[5];
    const float* W_r   = (const float*)d_in[6];
    const float* W_o   = (const float*)d_in[7];
    const float* gamma = (const float*)d_in[8];
    const float* beta  = (const float*)d_in[9];
    float* out = (float*)d_out;

    float *p_heads, *p_rk, *p_AC, *p_BD, *p_attn;
    __nv_bfloat16 *p_wbf, *p_rbf, *p_qkvt, *p_wrt, *p_wot;
    __nv_bfloat16 *p_qwbf, *p_qrbf, *p_kbf, *p_rkbf, *p_vtbf, *p_probbf, *p_vecbf;
    cudaGetSymbolAddress((void**)&p_heads, g_heads);
    cudaGetSymbolAddress((void**)&p_rk, g_rk);
    cudaGetSymbolAddress((void**)&p_AC, g_AC);
    cudaGetSymbolAddress((void**)&p_BD, g_BD);
    cudaGetSymbolAddress((void**)&p_attn, g_attn);
    cudaGetSymbolAddress((void**)&p_wbf, g_wbf);
    cudaGetSymbolAddress((void**)&p_rbf, g_rbf);
    cudaGetSymbolAddress((void**)&p_qkvt, g_qkvt);
    cudaGetSymbolAddress((void**)&p_wrt, g_wrt);
    cudaGetSymbolAddress((void**)&p_wot, g_wot);
    cudaGetSymbolAddress((void**)&p_qwbf, g_qwbf);
    cudaGetSymbolAddress((void**)&p_qrbf, g_qrbf);
    cudaGetSymbolAddress((void**)&p_kbf, g_kbf);
    cudaGetSymbolAddress((void**)&p_rkbf, g_rkbf);
    cudaGetSymbolAddress((void**)&p_vtbf, g_vtbf);
    cudaGetSymbolAddress((void**)&p_probbf, g_probbf);
    cudaGetSymbolAddress((void**)&p_vecbf, g_vecbf);

    cudaFuncSetAttribute(mma_gemm2<128, 128, 0>, cudaFuncAttributeMaxDynamicSharedMemorySize, 131072);
    cudaFuncSetAttribute(mma_gemm2<128, 64, 1>, cudaFuncAttributeMaxDynamicSharedMemorySize, 98304);

    const int FULLMASK = 0x7FFFFFFF;
    constexpr int SM128 = 131072;
    constexpr int SM64 = 98304;

    // (ordered so the ncu -s5 capture lands on a GEMM)
    split_kernel<<<4096 * 1024 / 256, 256>>>(w, p_wbf, 1024);                 // 0
    tsplit_kernel<<<dim3(16, 48), 256>>>(W_qkv, p_qkvt, 3072, 1024);          // 1

    // heads = w @ W_qkv
    mma_gemm2<128, 128, 0><<<dim3(24, 32, 1), 256, SM128>>>(                  // 2
        p_wbf, p_qkvt, p_heads, 1024, 2048, 2048, 3072, 0, 0, 0, 0, FULLMASK, 0);

    split_kernel<<<1024 * 1024 / 256, 256>>>(r, p_rbf, 1024);                 // 3
    tsplit_kernel<<<dim3(16, 16), 256>>>(W_r, p_wrt, 1024, 1024);             // 4

    // r_k = r @ W_r
    mma_gemm2<128, 128, 0><<<dim3(8, 8, 1), 256, SM128>>>(                    // 5
        p_rbf, p_wrt, p_rk, 1024, 2048, 2048, 1024, 0, 0, 0, 0, FULLMASK, 0);

    pack_qk_kernel<<<BN_TOT * QLEN * DH / 256, 256>>>(rwb, rrb);              // 6
    pack_rk_kernel<<<NH * QLEN * DH / 256, 256>>>();                          // 7
    pack_vt_kernel<<<dim3(16, 64), 256>>>();                                  // 8

    // AC = qw @ k^T (lower-tri tiles)
    mma_gemm2<128, 128, 0><<<dim3(36, 1, BN_TOT), 256, SM128>>>(              // 9
        p_qwbf, p_kbf, p_AC, 64, 128, 128, 1024,
        (long long)QLEN * 128, (long long)QLEN * 128, (long long)QLEN * QLEN,
        1, FULLMASK, 0);

    // BDrel = qr @ rk^T (anti-tri tiles, B batch = head)
    mma_gemm2<128, 128, 0><<<dim3(36, 1, BN_TOT), 256, SM128>>>(              // 10
        p_qrbf, p_rkbf, p_BD, 64, 128, 128, 1024,
        (long long)QLEN * 128, (long long)QLEN * 128, (long long)QLEN * QLEN,
        2, 15, 0);

    // fused shift+add+softmax -> split bf16 prob
    sm_softmax_kernel<<<BN_TOT * QLEN, 256>>>();                              // 11

    // vec = prob @ V (causal K-limit, split epilogue into g_vecbf)
    mma_gemm2<128, 64, 1><<<dim3(1, 8, BN_TOT), 256, SM64>>>(                 // 12
        p_probbf, p_vtbf, nullptr, 1024, 2048, 2048, 0,
        (long long)QLEN * 2048, (long long)DH * 2048, 0,
        0, FULLMASK, 1);

    tsplit_kernel<<<dim3(16, 16), 256>>>(W_o, p_wot, 1024, 1024);             // 13

    // attn = vec @ W_o
    mma_gemm2<128, 128, 0><<<dim3(8, 32, 1), 256, SM128>>>(                   // 14
        p_vecbf, p_wot, p_attn, 1024, 2048, 2048, 1024, 0, 0, 0, 0, FULLMASK, 0);

    // out = layernorm(w + attn)
    ln_kernel<<<4096, 256>>>(w, gamma, beta, out);                            // 15
}

// round 7
// speedup vs baseline: 3.1231x; 1.0727x over previous
#include <cuda_runtime.h>
#include <cuda_bf16.h>
#include <cstdint>
#include <cstddef>

#define QLEN 1024
#define BSZ 4
#define DM 1024
#define NH 16
#define DH 64
#define BN_TOT 64
#define NEGINF -1e30f
#define KDIM 1024

__device__ __forceinline__ uint32_t smem_to_u32(const void* p) {
    uint32_t a;
    asm("{ .reg .u64 t; cvta.to.shared.u64 t, %1; cvt.u32.u64 %0, t; }" : "=r"(a) : "l"(p));
    return a;
}
#define SWZ128(b) ((b) ^ (((b) >> 3) & 0x70))

__device__ __forceinline__ void ldm_x4(uint32_t r[4], uint32_t addr) {
    asm volatile("ldmatrix.sync.aligned.m8n8.x4.shared.b16 {%0,%1,%2,%3}, [%4];"
                 : "=r"(r[0]), "=r"(r[1]), "=r"(r[2]), "=r"(r[3]) : "r"(addr));
}
__device__ __forceinline__ void mma16816(float c[4], const uint32_t a[4], const uint32_t b[2]) {
    asm volatile("mma.sync.aligned.m16n8k16.row.col.f32.bf16.bf16.f32 "
                 "{%0,%1,%2,%3}, {%4,%5,%6,%7}, {%8,%9}, {%0,%1,%2,%3};"
                 : "+f"(c[0]), "+f"(c[1]), "+f"(c[2]), "+f"(c[3])
                 : "r"(a[0]), "r"(a[1]), "r"(a[2]), "r"(a[3]), "r"(b[0]), "r"(b[1]));
}
__device__ __forceinline__ void cp_async16(uint32_t saddr, const void* gptr) {
    asm volatile("cp.async.cg.shared.global [%0], [%1], 16;" :: "r"(saddr), "l"(gptr));
}
__device__ __forceinline__ void cp_commit() { asm volatile("cp.async.commit_group;"); }
template <int N>
__device__ __forceinline__ void cp_wait() { asm volatile("cp.async.wait_group %0;" :: "n"(N)); }

// ---------------- scratch ----------------
__device__ float g_heads[(size_t)QLEN * BSZ * 3 * DM];
__device__ float g_rk[(size_t)QLEN * DM];
__device__ float g_BD[(size_t)BN_TOT * QLEN * QLEN];
__device__ float g_attn[(size_t)QLEN * BSZ * DM];
__device__ __nv_bfloat16 g_wbf[(size_t)QLEN * BSZ * 2 * KDIM];
__device__ __nv_bfloat16 g_rbf[(size_t)QLEN * 2 * KDIM];
__device__ __nv_bfloat16 g_qkvt[(size_t)3 * DM * 2 * KDIM];
__device__ __nv_bfloat16 g_wrt[(size_t)DM * 2 * KDIM];
__device__ __nv_bfloat16 g_wot[(size_t)DM * 2 * KDIM];
__device__ __nv_bfloat16 g_qwbf[(size_t)BN_TOT * QLEN * 2 * DH];   // pre-scaled by 0.125
__device__ __nv_bfloat16 g_qrbf[(size_t)BN_TOT * QLEN * 2 * DH];   // pre-scaled by 0.125
__device__ __nv_bfloat16 g_kbf[(size_t)BN_TOT * QLEN * 2 * DH];
__device__ __nv_bfloat16 g_rkbf[(size_t)NH * QLEN * 2 * DH];
__device__ __nv_bfloat16 g_vtbf[(size_t)BN_TOT * DH * 2 * QLEN];
__device__ __nv_bfloat16 g_vecbf[(size_t)QLEN * BSZ * 2 * KDIM];

__device__ __forceinline__ void split2(float x, __nv_bfloat16& h, __nv_bfloat16& l) {
    h = __float2bfloat16(x);
    l = __float2bfloat16(x - __bfloat162float(h));
}

// ---------------- HMMA GEMM: load-once 3-pass hi/lo ----------------
// mode 0: full grid; 2: anti-tri 8x8 (BD)
template <int BM, int BN>
__global__ __launch_bounds__(256) void mma_gemm2(
    const __nv_bfloat16* __restrict__ A, const __nv_bfloat16* __restrict__ Bt,
    float* __restrict__ C, int K, int lda, int ldb, int ldc,
    long long sA, long long sB, long long sC, int mode, int bmask)
{
    extern __shared__ char smem[];
    const uint32_t smem_u32 = smem_to_u32(smem);
    constexpr int AHB = BM * 128;
    constexpr int BHB = BN * 128;
    constexpr int STG = 2 * AHB + 2 * BHB;
    constexpr int WN = BN / 2;
    constexpr int MT = 2;
    constexpr int NT = WN / 8;

    const int tid = threadIdx.x;
    const int lane = tid & 31, warp = tid >> 5;
    const int wm = warp & 3, wn = warp >> 2;
    const int bz = blockIdx.z;

    int m0, n0;
    if (mode == 0) {
        m0 = blockIdx.y * BM;
        n0 = blockIdx.x * BN;
    } else {
        int x = blockIdx.x;
        int it = (int)floorf((sqrtf(8.f * x + 1.f) - 1.f) * 0.5f);
        while ((it + 1) * (it + 2) / 2 <= x) ++it;
        while (it * (it + 1) / 2 > x) --it;
        int jt = x - it * (it + 1) / 2;
        m0 = it * BM;
        n0 = (7 - jt) * BN;
    }

    const __nv_bfloat16* Ab = A + (size_t)bz * sA;
    const __nv_bfloat16* Bb = Bt + (size_t)(bz & bmask) * sB;

    const int KT = K / 64;

    auto cp_stage = [&](int kt, int s) {
        const uint32_t base = smem_u32 + s * STG;
#pragma unroll
        for (int i = 0; i < BM / 32; i++) {
            int c = tid + i * 256, row = c >> 3, q = c & 7;
            uint32_t sw = SWZ128(row * 128 + q * 16);
            const __nv_bfloat16* gp = Ab + (size_t)(m0 + row) * lda + kt * 64 + q * 8;
            cp_async16(base + sw, gp);
            cp_async16(base + AHB + sw, gp + K);
        }
#pragma unroll
        for (int i = 0; i < BN / 32; i++) {
            int c = tid + i * 256, row = c >> 3, q = c & 7;
            uint32_t sw = SWZ128(row * 128 + q * 16);
            const __nv_bfloat16* gp = Bb + (size_t)(n0 + row) * ldb + kt * 64 + q * 8;
            cp_async16(base + 2 * AHB + sw, gp);
            cp_async16(base + 2 * AHB + BHB + sw, gp + K);
        }
        cp_commit();
    };

    float acc[MT][NT][4];
#pragma unroll
    for (int mt = 0; mt < MT; mt++)
#pragma unroll
        for (int nt = 0; nt < NT; nt++)
#pragma unroll
            for (int u = 0; u < 4; u++) acc[mt][nt][u] = 0.f;

    cp_stage(0, 0);
    if (KT > 1) cp_stage(1, 1);

    for (int t = 0; t < KT; t++) {
        const int s = t & 1;
        if (t < KT - 1) cp_wait<1>(); else cp_wait<0>();
        __syncthreads();

        const uint32_t ah = smem_u32 + s * STG;
        const uint32_t al = ah + AHB;
        const uint32_t bh = ah + 2 * AHB;
        const uint32_t bl = bh + BHB;
#pragma unroll
        for (int kk = 0; kk < 4; kk++) {
            const int seg = kk * 32 + (lane >> 4) * 16;
            uint32_t afh[MT][4], afl[MT][4], bfh[NT][2], bfl[NT][2];
#pragma unroll
            for (int mt = 0; mt < MT; mt++) {
                int sw = SWZ128((wm * 32 + mt * 16 + (lane & 15)) * 128 + seg);
                ldm_x4(afh[mt], ah + sw);
                ldm_x4(afl[mt], al + sw);
            }
#pragma unroll
            for (int p = 0; p < NT / 2; p++) {
                int sw = SWZ128((wn * WN + p * 16 + (lane & 15)) * 128 + seg);
                uint32_t r[4];
                ldm_x4(r, bh + sw);
                bfh[2 * p][0] = r[0]; bfh[2 * p][1] = r[2];
                bfh[2 * p + 1][0] = r[1]; bfh[2 * p + 1][1] = r[3];
                ldm_x4(r, bl + sw);
                bfl[2 * p][0] = r[0]; bfl[2 * p][1] = r[2];
                bfl[2 * p + 1][0] = r[1]; bfl[2 * p + 1][1] = r[3];
            }
#pragma unroll
            for (int mt = 0; mt < MT; mt++)
#pragma unroll
                for (int nt = 0; nt < NT; nt++) {
                    mma16816(acc[mt][nt], afh[mt], bfh[nt]);
                    mma16816(acc[mt][nt], afl[mt], bfh[nt]);
                    mma16816(acc[mt][nt], afh[mt], bfl[nt]);
                }
        }
        __syncthreads();
        if (t + 2 < KT) cp_stage(t + 2, s);
    }

    float* Cb = C + (size_t)bz * sC;
#pragma unroll
    for (int mt = 0; mt < MT; mt++)
#pragma unroll
        for (int nt = 0; nt < NT; nt++) {
            int mrow = m0 + wm * 32 + mt * 16 + (lane >> 2);
            int col = n0 + wn * WN + nt * 8 + (lane & 3) * 2;
            *(float2*)&Cb[(size_t)mrow * ldc + col] = make_float2(acc[mt][nt][0], acc[mt][nt][1]);
            *(float2*)&Cb[(size_t)(mrow + 8) * ldc + col] = make_float2(acc[mt][nt][2], acc[mt][nt][3]);
        }
}

// ---------------- flash kernel: AC(HMMA) + shifted BD + online softmax + PV ----------------
__global__ __launch_bounds__(256) void flash_kernel()
{
    extern __shared__ char smem[];
    const uint32_t su = smem_to_u32(smem);
    constexpr int OFF_QWH = 0, OFF_QWL = 16384;
    constexpr int OFF_K = 32768;          // two stages of 32768 (hi | lo 16384)
    constexpr int OFF_VH = 98304;         // 2 chunks * 8192
    constexpr int OFF_VL = 114688;
    constexpr int OFF_PH = 131072;        // 2 chunks * 16384
    constexpr int OFF_PL = 163840;
    constexpr int OFF_RA = 196608;
    constexpr int OFF_RB = 197632;

    const int tid = threadIdx.x;
    const int lane = tid & 31, warp = tid >> 5;
    const int wm = warp & 3, wn = warp >> 2;
    const int bn = blockIdx.z;
    const int it = 7 - blockIdx.x;        // heavy tiles first
    const int i0 = it * 128;

    const __nv_bfloat16* qw = g_qwbf + (size_t)bn * QLEN * 128;
    const __nv_bfloat16* kb = g_kbf + (size_t)bn * QLEN * 128;
    const __nv_bfloat16* vt = g_vtbf + (size_t)bn * DH * 2048;
    const float* bdb = g_BD + (size_t)bn * QLEN * QLEN;
    float* redA = (float*)(smem + OFF_RA);
    float* redB = (float*)(smem + OFF_RB);

    // preload QW hi/lo + K tile 0 (one cp.async group)
#pragma unroll
    for (int i = 0; i < 4; i++) {
        int c = tid + i * 256, row = c >> 3, q = c & 7;
        uint32_t sw = SWZ128(row * 128 + q * 16);
        const __nv_bfloat16* gp = qw + (size_t)(i0 + row) * 128 + q * 8;
        cp_async16(su + OFF_QWH + sw, gp);
        cp_async16(su + OFF_QWL + sw, gp + 64);
    }
#pragma unroll
    for (int i = 0; i < 4; i++) {
        int c = tid + i * 256, row = c >> 3, q = c & 7;
        uint32_t sw = SWZ128(row * 128 + q * 16);
        const __nv_bfloat16* gp = kb + (size_t)row * 128 + q * 8;
        cp_async16(su + OFF_K + sw, gp);
        cp_async16(su + OFF_K + 16384 + sw, gp + 64);
    }
    cp_commit();

    float acc_o[2][4][4];
#pragma unroll
    for (int mt = 0; mt < 2; mt++)
#pragma unroll
        for (int nt = 0; nt < 4; nt++)
#pragma unroll
            for (int u = 0; u < 4; u++) acc_o[mt][nt][u] = 0.f;
    float m_old[4], l_run[4];
#pragma unroll
    for (int i = 0; i < 4; i++) { m_old[i] = NEGINF; l_run[i] = 0.f; }

    for (int jt = 0; jt <= it; jt++) {
        const int s = jt & 1;
        const int j0 = jt * 128;
        const bool more = (jt < it);
        cp_wait<0>();
        __syncthreads();

        // issue V_jt (group), then next K (group)
#pragma unroll
        for (int i = 0; i < 8; i++) {
            int c = tid + i * 256;
            int q = c & 7, row = (c >> 3) & 63, ch = (c >> 9) & 1, hf = c >> 10;
            uint32_t sw = SWZ128(row * 128 + q * 16) + ch * 8192;
            const __nv_bfloat16* gp = vt + (size_t)row * 2048 + hf * 1024 + j0 + ch * 64 + q * 8;
            cp_async16(su + (hf ? OFF_VL : OFF_VH) + sw, gp);
        }
        cp_commit();
        if (more) {
            int j0n = j0 + 128;
#pragma unroll
            for (int i = 0; i < 4; i++) {
                int c = tid + i * 256, row = c >> 3, q = c & 7;
                uint32_t sw = SWZ128(row * 128 + q * 16);
                const __nv_bfloat16* gp = kb + (size_t)(j0n + row) * 128 + q * 8;
                cp_async16(su + OFF_K + (s ^ 1) * 32768 + sw, gp);
                cp_async16(su + OFF_K + (s ^ 1) * 32768 + 16384 + sw, gp + 64);
            }
            cp_commit();
        }

        // ---- S = qw @ k^T (3-term) ----
        float accS[2][8][4];
#pragma unroll
        for (int mt = 0; mt < 2; mt++)
#pragma unroll
            for (int nt = 0; nt < 8; nt++)
#pragma unroll
                for (int u = 0; u < 4; u++) accS[mt][nt][u] = 0.f;

        const uint32_t ah_ = su + OFF_QWH, al_ = su + OFF_QWL;
        const uint32_t bh_ = su + OFF_K + s * 32768, bl_ = bh_ + 16384;
#pragma unroll
        for (int kk = 0; kk < 4; kk++) {
            const int seg = kk * 32 + (lane >> 4) * 16;
            uint32_t afh[2][4], afl[2][4], bfh[8][2], bfl[8][2];
#pragma unroll
            for (int mt = 0; mt < 2; mt++) {
                int sw = SWZ128((wm * 32 + mt * 16 + (lane & 15)) * 128 + seg);
                ldm_x4(afh[mt], ah_ + sw);
                ldm_x4(afl[mt], al_ + sw);
            }
#pragma unroll
            for (int p = 0; p < 4; p++) {
                int sw = SWZ128((wn * 64 + p * 16 + (lane & 15)) * 128 + seg);
                uint32_t r[4];
                ldm_x4(r, bh_ + sw);
                bfh[2 * p][0] = r[0]; bfh[2 * p][1] = r[2];
                bfh[2 * p + 1][0] = r[1]; bfh[2 * p + 1][1] = r[3];
                ldm_x4(r, bl_ + sw);
                bfl[2 * p][0] = r[0]; bfl[2 * p][1] = r[2];
                bfl[2 * p + 1][0] = r[1]; bfl[2 * p + 1][1] = r[3];
            }
#pragma unroll
            for (int mt = 0; mt < 2; mt++)
#pragma unroll
                for (int nt = 0; nt < 8; nt++) {
                    mma16816(accS[mt][nt], afh[mt], bfh[nt]);
                    mma16816(accS[mt][nt], afl[mt], bfh[nt]);
                    mma16816(accS[mt][nt], afh[mt], bfl[nt]);
                }
        }

        // ---- + shifted BD, causal mask (qw/qr pre-scaled by 0.125) ----
#pragma unroll
        for (int mt = 0; mt < 2; mt++)
#pragma unroll
            for (int hf = 0; hf < 2; hf++) {
                int row_l = wm * 32 + mt * 16 + (lane >> 2) + hf * 8;
                int gi = i0 + row_l;
                const float* bdrow = bdb + (size_t)gi * 1024 + (1023 - gi) + j0;
#pragma unroll
                for (int nt = 0; nt < 8; nt++)
#pragma unroll
                    for (int e = 0; e < 2; e++) {
                        int col = wn * 64 + nt * 8 + (lane & 3) * 2 + e;
                        int gj = j0 + col;
                        float v = (gj <= gi) ? (accS[mt][nt][hf * 2 + e] + bdrow[col]) : NEGINF;
                        accS[mt][nt][hf * 2 + e] = v;
                    }
            }

        // ---- online softmax: row max ----
        float m_new[4], alpha[4];
#pragma unroll
        for (int mt = 0; mt < 2; mt++)
#pragma unroll
            for (int hf = 0; hf < 2; hf++) {
                float mx = NEGINF;
#pragma unroll
                for (int nt = 0; nt < 8; nt++)
                    mx = fmaxf(mx, fmaxf(accS[mt][nt][hf * 2], accS[mt][nt][hf * 2 + 1]));
                mx = fmaxf(mx, __shfl_xor_sync(0xffffffffu, mx, 1));
                mx = fmaxf(mx, __shfl_xor_sync(0xffffffffu, mx, 2));
                if ((lane & 3) == 0) redA[wn * 128 + wm * 32 + mt * 16 + (lane >> 2) + hf * 8] = mx;
                m_new[mt * 2 + hf] = mx;
            }
        __syncthreads();
#pragma unroll
        for (int mt = 0; mt < 2; mt++)
#pragma unroll
            for (int hf = 0; hf < 2; hf++) {
                int row_l = wm * 32 + mt * 16 + (lane >> 2) + hf * 8;
                int idx = mt * 2 + hf;
                float comb = fmaxf(redA[row_l], redA[128 + row_l]);
                float mn = fmaxf(m_old[idx], comb);
                alpha[idx] = __expf(m_old[idx] - mn);
                m_new[idx] = mn;
                m_old[idx] = mn;                     // FIX (R6 bug): advance softmax state
            }

        // ---- p = exp(s - m), row sums ----
#pragma unroll
        for (int mt = 0; mt < 2; mt++)
#pragma unroll
            for (int hf = 0; hf < 2; hf++) {
                int idx = mt * 2 + hf;
                float ssum = 0.f;
#pragma unroll
                for (int nt = 0; nt < 8; nt++)
#pragma unroll
                    for (int e = 0; e < 2; e++) {
                        float p = __expf(accS[mt][nt][hf * 2 + e] - m_new[idx]);
                        accS[mt][nt][hf * 2 + e] = p;
                        ssum += p;
                    }
                ssum += __shfl_xor_sync(0xffffffffu, ssum, 1);
                ssum += __shfl_xor_sync(0xffffffffu, ssum, 2);
                if ((lane & 3) == 0) redB[wn * 128 + wm * 32 + mt * 16 + (lane >> 2) + hf * 8] = ssum;
            }
        __syncthreads();
#pragma unroll
        for (int mt = 0; mt < 2; mt++)
#pragma unroll
            for (int hf = 0; hf < 2; hf++) {
                int row_l = wm * 32 + mt * 16 + (lane >> 2) + hf * 8;
                int idx = mt * 2 + hf;
                l_run[idx] = l_run[idx] * alpha[idx] + redB[row_l] + redB[128 + row_l];
            }

        // ---- rescale acc_o ----
#pragma unroll
        for (int mt = 0; mt < 2; mt++)
#pragma unroll
            for (int nt = 0; nt < 4; nt++)
#pragma unroll
                for (int u = 0; u < 4; u++) acc_o[mt][nt][u] *= alpha[mt * 2 + (u >> 1)];

        // ---- store P (split bf16, two 64-col chunks; chunk = wn) ----
#pragma unroll
        for (int mt = 0; mt < 2; mt++)
#pragma unroll
            for (int hf = 0; hf < 2; hf++) {
                int row_l = wm * 32 + mt * 16 + (lane >> 2) + hf * 8;
#pragma unroll
                for (int nt = 0; nt < 8; nt++) {
                    float v0 = accS[mt][nt][hf * 2], v1 = accS[mt][nt][hf * 2 + 1];
                    __nv_bfloat16 h0, l0, h1, l1;
                    split2(v0, h0, l0);
                    split2(v1, h1, l1);
                    uint32_t off = SWZ128(row_l * 128 + (nt * 8 + (lane & 3) * 2) * 2);
                    *(__nv_bfloat162*)(smem + OFF_PH + wn * 16384 + off) = __nv_bfloat162(h0, h1);
                    *(__nv_bfloat162*)(smem + OFF_PL + wn * 16384 + off) = __nv_bfloat162(l0, l1);
                }
            }
        if (more) cp_wait<1>(); else cp_wait<0>();
        __syncthreads();   // P + V visible

        // ---- PV: acc_o += P @ V ----
#pragma unroll
        for (int kk = 0; kk < 8; kk++) {
            const int ch = kk >> 2;
            const int seg = (kk & 3) * 32 + (lane >> 4) * 16;
            uint32_t pah[2][4], pal[2][4], vbh[4][2], vbl[4][2];
#pragma unroll
            for (int mt = 0; mt < 2; mt++) {
                int sw = SWZ128((wm * 32 + mt * 16 + (lane & 15)) * 128 + seg);
                ldm_x4(pah[mt], su + OFF_PH + ch * 16384 + sw);
                ldm_x4(pal[mt], su + OFF_PL + ch * 16384 + sw);
            }
#pragma unroll
            for (int p = 0; p < 2; p++) {
                int sw = SWZ128((wn * 32 + p * 16 + (lane & 15)) * 128 + seg);
                uint32_t r[4];
                ldm_x4(r, su + OFF_VH + ch * 8192 + sw);
                vbh[2 * p][0] = r[0]; vbh[2 * p][1] = r[2];
                vbh[2 * p + 1][0] = r[1]; vbh[2 * p + 1][1] = r[3];
                ldm_x4(r, su + OFF_VL + ch * 8192 + sw);
                vbl[2 * p][0] = r[0]; vbl[2 * p][1] = r[2];
                vbl[2 * p + 1][0] = r[1]; vbl[2 * p + 1][1] = r[3];
            }
#pragma unroll
            for (int mt = 0; mt < 2; mt++)
#pragma unroll
                for (int nt = 0; nt < 4; nt++) {
                    mma16816(acc_o[mt][nt], pah[mt], vbh[nt]);
                    mma16816(acc_o[mt][nt], pal[mt], vbh[nt]);
                    mma16816(acc_o[mt][nt], pah[mt], vbl[nt]);
                }
        }
        __syncthreads();   // V/P free for next iter
        (void)ah_; (void)al_;
    }

    // ---- epilogue: vec = acc_o / l, split bf16 into g_vecbf ----
    const int b = bn >> 4, n = bn & 15;
    float inv[4];
#pragma unroll
    for (int i = 0; i < 4; i++) inv[i] = 1.f / l_run[i];
#pragma unroll
    for (int mt = 0; mt < 2; mt++)
#pragma unroll
        for (int nt = 0; nt < 4; nt++)
#pragma unroll
            for (int hf = 0; hf < 2; hf++) {
                int row_l = wm * 32 + mt * 16 + (lane >> 2) + hf * 8;
                int gi = i0 + row_l;
                int d0 = wn * 32 + nt * 8 + (lane & 3) * 2;
                float v0 = acc_o[mt][nt][hf * 2] * inv[mt * 2 + hf];
                float v1 = acc_o[mt][nt][hf * 2 + 1] * inv[mt * 2 + hf];
                __nv_bfloat16 h0, l0, h1, l1;
                split2(v0, h0, l0);
                split2(v1, h1, l1);
                size_t orow = (size_t)(gi * 4 + b) * 2048 + n * 64 + d0;
                *(__nv_bfloat162*)&g_vecbf[orow] = __nv_bfloat162(h0, h1);
                *(__nv_bfloat162*)&g_vecbf[orow + 1024] = __nv_bfloat162(l0, l1);
            }
}

// ---------------- split / transpose / pack kernels ----------------
__global__ void split_kernel(const float* __restrict__ X, __nv_bfloat16* __restrict__ Y, int cols)
{
    int idx = blockIdx.x * 256 + threadIdx.x;
    int row = idx / cols, col = idx - row * cols;
    __nv_bfloat16 h, l;
    split2(X[idx], h, l);
    Y[(size_t)row * 2 * cols + col] = h;
    Y[(size_t)row * 2 * cols + cols + col] = l;
}

__global__ __launch_bounds__(256) void tsplit_kernel(const float* __restrict__ X,
                                                     __nv_bfloat16* __restrict__ Y, int N, int K)
{
    __shared__ float sm[64][65];
    int k0 = blockIdx.x * 64, n0 = blockIdx.y * 64;
    int tid = threadIdx.x;
    for (int e = tid; e < 4096; e += 256) {
        int r = e >> 6, c = e & 63;
        sm[c][r] = X[(size_t)(k0 + r) * N + n0 + c];
    }
    __syncthreads();
    for (int e = tid; e < 4096; e += 256) {
        int r = e >> 6, c = e & 63;
        __nv_bfloat16 h, l;
        split2(sm[r][c], h, l);
        Y[(size_t)(n0 + r) * 2 * K + k0 + c] = h;
        Y[(size_t)(n0 + r) * 2 * K + K + k0 + c] = l;
    }
}

__global__ void pack_qk_kernel(const float* __restrict__ rwb, const float* __restrict__ rrb)
{
    int idx = blockIdx.x * 256 + threadIdx.x;
    int d = idx & 63, i = (idx >> 6) & 1023, bn = idx >> 16;
    int b = bn >> 4, n = bn & 15;
    size_t hbase = (size_t)(i * 4 + b) * 3072 + n * 64 + d;
    float q = g_heads[hbase];
    float k = g_heads[hbase + 1024];
    size_t o = ((size_t)bn * QLEN + i) * 128 + d;
    __nv_bfloat16 h, l;
    split2((q + rwb[n * 64 + d]) * 0.125f, h, l);
    g_qwbf[o] = h; g_qwbf[o + 64] = l;
    split2((q + rrb[n * 64 + d]) * 0.125f, h, l);
    g_qrbf[o] = h; g_qrbf[o + 64] = l;
    split2(k, h, l);
    g_kbf[o] = h; g_kbf[o + 64] = l;
}

__global__ void pack_rk_kernel()
{
    int idx = blockIdx.x * 256 + threadIdx.x;
    int d = idx & 63, m = (idx >> 6) & 1023, n = idx >> 16;
    __nv_bfloat16 h, l;
    split2(g_rk[(size_t)m * 1024 + n * 64 + d], h, l);
    size_t o = ((size_t)n * QLEN + m) * 128 + d;
    g_rkbf[o] = h; g_rkbf[o + 64] = l;
}

__global__ __launch_bounds__(256) void pack_vt_kernel()
{
    __shared__ float sm[64][65];
    int bn = blockIdx.y, b = bn >> 4, n = bn & 15;
    int j0 = blockIdx.x * 64;
    int tid = threadIdx.x;
    for (int e = tid; e < 4096; e += 256) {
        int jj = e >> 6, d = e & 63;
        sm[d][jj] = g_heads[(size_t)((j0 + jj) * 4 + b) * 3072 + 2048 + n * 64 + d];
    }
    __syncthreads();
    for (int e = tid; e < 4096; e += 256) {
        int d = e >> 6, jj = e & 63;
        __nv_bfloat16 h, l;
        split2(sm[d][jj], h, l);
        g_vtbf[((size_t)bn * 64 + d) * 2048 + j0 + jj] = h;
        g_vtbf[((size_t)bn * 64 + d) * 2048 + 1024 + j0 + jj] = l;
    }
}

// ---------------- residual + layernorm ----------------
__global__ __launch_bounds__(256) void ln_kernel(
    const float* __restrict__ w, const float* __restrict__ gamma,
    const float* __restrict__ beta, float* __restrict__ out)
{
    int row = blockIdx.x;
    const float* wr = w + (size_t)row * DM;
    const float* ar = g_attn + (size_t)row * DM;
    int tid = threadIdx.x;

    float x[4];
    float s = 0.f, s2 = 0.f;
#pragma unroll
    for (int u = 0; u < 4; u++) {
        int c = tid + u * 256;
        x[u] = wr[c] + ar[c];
        s += x[u];
        s2 += x[u] * x[u];
    }
    __shared__ float rs[256], rs2[256];
    rs[tid] = s; rs2[tid] = s2;
    __syncthreads();
    for (int t = 128; t > 0; t >>= 1) {
        if (tid < t) { rs[tid] += rs[tid + t]; rs2[tid] += rs2[tid + t]; }
        __syncthreads();
    }
    float mu = rs[0] * (1.f / DM);
    float var = rs2[0] * (1.f / DM) - mu * mu;
    float rstd = rsqrtf(var + 1e-5f);
#pragma unroll
    for (int u = 0; u < 4; u++) {
        int c = tid + u * 256;
        out[(size_t)row * DM + c] = (x[u] - mu) * rstd * gamma[c] + beta[c];
    }
}

// ---------------- launch ----------------
extern "C" void kernel_launch(void* const* d_in, const int* in_sizes, int n_in,
                              void* d_out, int out_size)
{
    const float* w     = (const float*)d_in[0];
    const float* r     = (const float*)d_in[1];
    const float* rwb   = (const float*)d_in[2];
    const float* rrb   = (const float*)d_in[3];
    const float* W_qkv = (const float*)d_in[5];
    const float* W_r   = (const float*)d_in[6];
    const float* W_o   = (const float*)d_in[7];
    const float* gamma = (const float*)d_in[8];
    const float* beta  = (const float*)d_in[9];
    float* out = (float*)d_out;

    float *p_heads, *p_rk, *p_BD, *p_attn;
    __nv_bfloat16 *p_wbf, *p_rbf, *p_qkvt, *p_wrt, *p_wot;
    __nv_bfloat16 *p_qwbf, *p_qrbf, *p_kbf, *p_rkbf, *p_vtbf, *p_vecbf;
    cudaGetSymbolAddress((void**)&p_heads, g_heads);
    cudaGetSymbolAddress((void**)&p_rk, g_rk);
    cudaGetSymbolAddress((void**)&p_BD, g_BD);
    cudaGetSymbolAddress((void**)&p_attn, g_attn);
    cudaGetSymbolAddress((void**)&p_wbf, g_wbf);
    cudaGetSymbolAddress((void**)&p_rbf, g_rbf);
    cudaGetSymbolAddress((void**)&p_qkvt, g_qkvt);
    cudaGetSymbolAddress((void**)&p_wrt, g_wrt);
    cudaGetSymbolAddress((void**)&p_wot, g_wot);
    cudaGetSymbolAddress((void**)&p_qwbf, g_qwbf);
    cudaGetSymbolAddress((void**)&p_qrbf, g_qrbf);
    cudaGetSymbolAddress((void**)&p_kbf, g_kbf);
    cudaGetSymbolAddress((void**)&p_rkbf, g_rkbf);
    cudaGetSymbolAddress((void**)&p_vtbf, g_vtbf);
    cudaGetSymbolAddress((void**)&p_vecbf, g_vecbf);

    cudaFuncSetAttribute(mma_gemm2<128, 128>, cudaFuncAttributeMaxDynamicSharedMemorySize, 131072);
    cudaFuncSetAttribute(flash_kernel, cudaFuncAttributeMaxDynamicSharedMemorySize, 198656);

    const int FULLMASK = 0x7FFFFFFF;
    constexpr int SM128 = 131072;

    split_kernel<<<4096 * 1024 / 256, 256>>>(w, p_wbf, 1024);                 // 0
    tsplit_kernel<<<dim3(16, 48), 256>>>(W_qkv, p_qkvt, 3072, 1024);          // 1

    mma_gemm2<128, 128><<<dim3(24, 32, 1), 256, SM128>>>(                     // 2: heads
        p_wbf, p_qkvt, p_heads, 1024, 2048, 2048, 3072, 0, 0, 0, 0, FULLMASK);

    split_kernel<<<1024 * 1024 / 256, 256>>>(r, p_rbf, 1024);                 // 3
    tsplit_kernel<<<dim3(16, 16), 256>>>(W_r, p_wrt, 1024, 1024);             // 4

    mma_gemm2<128, 128><<<dim3(8, 8, 1), 256, SM128>>>(                       // 5: r_k
        p_rbf, p_wrt, p_rk, 1024, 2048, 2048, 1024, 0, 0, 0, 0, FULLMASK);

    pack_qk_kernel<<<BN_TOT * QLEN * DH / 256, 256>>>(rwb, rrb);              // 6
    pack_rk_kernel<<<NH * QLEN * DH / 256, 256>>>();                          // 7
    pack_vt_kernel<<<dim3(16, 64), 256>>>();                                  // 8

    // BDrel = qr @ rk^T (anti-tri tiles, B batch = head), pre-scaled 0.125
    mma_gemm2<128, 128><<<dim3(36, 1, BN_TOT), 256, SM128>>>(                 // 9
        p_qrbf, p_rkbf, p_BD, 64, 128, 128, 1024,
        (long long)QLEN * 128, (long long)QLEN * 128, (long long)QLEN * QLEN,
        2, 15);

    // fused AC + BD + softmax + PV
    flash_kernel<<<dim3(8, 1, BN_TOT), 256, 198656>>>();                      // 10

    tsplit_kernel<<<dim3(16, 16), 256>>>(W_o, p_wot, 1024, 1024);             // 11

    mma_gemm2<128, 128><<<dim3(8, 32, 1), 256, SM128>>>(                      // 12: attn
        p_vecbf, p_wot, p_attn, 1024, 2048, 2048, 1024, 0, 0, 0, 0, FULLMASK);

    ln_kernel<<<4096, 256>>>(w, gamma, beta, out);                            // 13
}

// round 9
// speedup vs baseline: 3.1363x; 1.0042x over previous
#include <cuda_runtime.h>
#include <cuda_bf16.h>
#include <cstdint>
#include <cstddef>

#define QLEN 1024
#define BSZ 4
#define DM 1024
#define NH 16
#define DH 64
#define BN_TOT 64
#define NEGINF -1e30f
#define KDIM 1024

__device__ __forceinline__ uint32_t smem_to_u32(const void* p) {
    uint32_t a;
    asm("{ .reg .u64 t; cvta.to.shared.u64 t, %1; cvt.u32.u64 %0, t; }" : "=r"(a) : "l"(p));
    return a;
}
#define SWZ128(b) ((b) ^ (((b) >> 3) & 0x70))

__device__ __forceinline__ void ldm_x4(uint32_t r[4], uint32_t addr) {
    asm volatile("ldmatrix.sync.aligned.m8n8.x4.shared.b16 {%0,%1,%2,%3}, [%4];"
                 : "=r"(r[0]), "=r"(r[1]), "=r"(r[2]), "=r"(r[3]) : "r"(addr));
}
__device__ __forceinline__ void mma16816(float c[4], const uint32_t a[4], const uint32_t b[2]) {
    asm volatile("mma.sync.aligned.m16n8k16.row.col.f32.bf16.bf16.f32 "
                 "{%0,%1,%2,%3}, {%4,%5,%6,%7}, {%8,%9}, {%0,%1,%2,%3};"
                 : "+f"(c[0]), "+f"(c[1]), "+f"(c[2]), "+f"(c[3])
                 : "r"(a[0]), "r"(a[1]), "r"(a[2]), "r"(a[3]), "r"(b[0]), "r"(b[1]));
}
__device__ __forceinline__ void cp_async16(uint32_t saddr, const void* gptr) {
    asm volatile("cp.async.cg.shared.global [%0], [%1], 16;" :: "r"(saddr), "l"(gptr));
}
__device__ __forceinline__ void cp_commit() { asm volatile("cp.async.commit_group;"); }
template <int N>
__device__ __forceinline__ void cp_wait() { asm volatile("cp.async.wait_group %0;" :: "n"(N)); }

// ---------------- scratch ----------------
__device__ float g_heads[(size_t)QLEN * BSZ * 3 * DM];
__device__ float g_rk[(size_t)QLEN * DM];
__device__ float g_BD[(size_t)BN_TOT * QLEN * QLEN];
__device__ float g_attn[(size_t)QLEN * BSZ * DM];
__device__ __nv_bfloat16 g_wbf[(size_t)QLEN * BSZ * 2 * KDIM];
__device__ __nv_bfloat16 g_rbf[(size_t)QLEN * 2 * KDIM];
__device__ __nv_bfloat16 g_qkvt[(size_t)3 * DM * 2 * KDIM];
__device__ __nv_bfloat16 g_wrt[(size_t)DM * 2 * KDIM];
__device__ __nv_bfloat16 g_wot[(size_t)DM * 2 * KDIM];
__device__ __nv_bfloat16 g_qwbf[(size_t)BN_TOT * QLEN * 2 * DH];   // pre-scaled by 0.125
__device__ __nv_bfloat16 g_qrbf[(size_t)BN_TOT * QLEN * 2 * DH];   // pre-scaled by 0.125
__device__ __nv_bfloat16 g_kbf[(size_t)BN_TOT * QLEN * 2 * DH];
__device__ __nv_bfloat16 g_rkbf[(size_t)NH * QLEN * 2 * DH];
__device__ __nv_bfloat16 g_vtbf[(size_t)BN_TOT * DH * 2 * QLEN];
__device__ __nv_bfloat16 g_vecbf[(size_t)QLEN * BSZ * 2 * KDIM];

__device__ __forceinline__ void split2(float x, __nv_bfloat16& h, __nv_bfloat16& l) {
    h = __float2bfloat16(x);
    l = __float2bfloat16(x - __bfloat162float(h));
}

// ---------------- HMMA GEMM: load-once 3-pass hi/lo ----------------
// mode 0: full grid; 2: anti-tri 8x8 (BD)
template <int BM, int BN>
__global__ __launch_bounds__(256) void mma_gemm2(
    const __nv_bfloat16* __restrict__ A, const __nv_bfloat16* __restrict__ Bt,
    float* __restrict__ C, int K, int lda, int ldb, int ldc,
    long long sA, long long sB, long long sC, int mode, int bmask)
{
    extern __shared__ char smem[];
    const uint32_t smem_u32 = smem_to_u32(smem);
    constexpr int AHB = BM * 128;
    constexpr int BHB = BN * 128;
    constexpr int STG = 2 * AHB + 2 * BHB;
    constexpr int WN = BN / 2;
    constexpr int MT = 2;
    constexpr int NT = WN / 8;

    const int tid = threadIdx.x;
    const int lane = tid & 31, warp = tid >> 5;
    const int wm = warp & 3, wn = warp >> 2;
    const int bz = blockIdx.z;

    int m0, n0;
    if (mode == 0) {
        m0 = blockIdx.y * BM;
        n0 = blockIdx.x * BN;
    } else {
        int x = blockIdx.x;
        int it = (int)floorf((sqrtf(8.f * x + 1.f) - 1.f) * 0.5f);
        while ((it + 1) * (it + 2) / 2 <= x) ++it;
        while (it * (it + 1) / 2 > x) --it;
        int jt = x - it * (it + 1) / 2;
        m0 = it * BM;
        n0 = (7 - jt) * BN;
    }

    const __nv_bfloat16* Ab = A + (size_t)bz * sA;
    const __nv_bfloat16* Bb = Bt + (size_t)(bz & bmask) * sB;

    const int KT = K / 64;

    auto cp_stage = [&](int kt, int s) {
        const uint32_t base = smem_u32 + s * STG;
#pragma unroll
        for (int i = 0; i < BM / 32; i++) {
            int c = tid + i * 256, row = c >> 3, q = c & 7;
            uint32_t sw = SWZ128(row * 128 + q * 16);
            const __nv_bfloat16* gp = Ab + (size_t)(m0 + row) * lda + kt * 64 + q * 8;
            cp_async16(base + sw, gp);
            cp_async16(base + AHB + sw, gp + K);
        }
#pragma unroll
        for (int i = 0; i < BN / 32; i++) {
            int c = tid + i * 256, row = c >> 3, q = c & 7;
            uint32_t sw = SWZ128(row * 128 + q * 16);
            const __nv_bfloat16* gp = Bb + (size_t)(n0 + row) * ldb + kt * 64 + q * 8;
            cp_async16(base + 2 * AHB + sw, gp);
            cp_async16(base + 2 * AHB + BHB + sw, gp + K);
        }
        cp_commit();
    };

    float acc[MT][NT][4];
#pragma unroll
    for (int mt = 0; mt < MT; mt++)
#pragma unroll
        for (int nt = 0; nt < NT; nt++)
#pragma unroll
            for (int u = 0; u < 4; u++) acc[mt][nt][u] = 0.f;

    cp_stage(0, 0);
    if (KT > 1) cp_stage(1, 1);

    for (int t = 0; t < KT; t++) {
        const int s = t & 1;
        if (t < KT - 1) cp_wait<1>(); else cp_wait<0>();
        __syncthreads();

        const uint32_t ah = smem_u32 + s * STG;
        const uint32_t al = ah + AHB;
        const uint32_t bh = ah + 2 * AHB;
        const uint32_t bl = bh + BHB;
#pragma unroll
        for (int kk = 0; kk < 4; kk++) {
            const int seg = kk * 32 + (lane >> 4) * 16;
            uint32_t afh[MT][4], afl[MT][4], bfh[NT][2], bfl[NT][2];
#pragma unroll
            for (int mt = 0; mt < MT; mt++) {
                int sw = SWZ128((wm * 32 + mt * 16 + (lane & 15)) * 128 + seg);
                ldm_x4(afh[mt], ah + sw);
                ldm_x4(afl[mt], al + sw);
            }
#pragma unroll
            for (int p = 0; p < NT / 2; p++) {
                int sw = SWZ128((wn * WN + p * 16 + (lane & 15)) * 128 + seg);
                uint32_t r[4];
                ldm_x4(r, bh + sw);
                bfh[2 * p][0] = r[0]; bfh[2 * p][1] = r[2];
                bfh[2 * p + 1][0] = r[1]; bfh[2 * p + 1][1] = r[3];
                ldm_x4(r, bl + sw);
                bfl[2 * p][0] = r[0]; bfl[2 * p][1] = r[2];
                bfl[2 * p + 1][0] = r[1]; bfl[2 * p + 1][1] = r[3];
            }
            // three separate sweeps: dependent writes to any acc pair are
            // separated by MT*NT-1 other HMMAs (breaks RAW serialization)
#pragma unroll
            for (int mt = 0; mt < MT; mt++)
#pragma unroll
                for (int nt = 0; nt < NT; nt++)
                    mma16816(acc[mt][nt], afh[mt], bfh[nt]);
#pragma unroll
            for (int mt = 0; mt < MT; mt++)
#pragma unroll
                for (int nt = 0; nt < NT; nt++)
                    mma16816(acc[mt][nt], afl[mt], bfh[nt]);
#pragma unroll
            for (int mt = 0; mt < MT; mt++)
#pragma unroll
                for (int nt = 0; nt < NT; nt++)
                    mma16816(acc[mt][nt], afh[mt], bfl[nt]);
        }
        __syncthreads();
        if (t + 2 < KT) cp_stage(t + 2, s);
    }

    float* Cb = C + (size_t)bz * sC;
#pragma unroll
    for (int mt = 0; mt < MT; mt++)
#pragma unroll
        for (int nt = 0; nt < NT; nt++) {
            int mrow = m0 + wm * 32 + mt * 16 + (lane >> 2);
            int col = n0 + wn * WN + nt * 8 + (lane & 3) * 2;
            *(float2*)&Cb[(size_t)mrow * ldc + col] = make_float2(acc[mt][nt][0], acc[mt][nt][1]);
            *(float2*)&Cb[(size_t)(mrow + 8) * ldc + col] = make_float2(acc[mt][nt][2], acc[mt][nt][3]);
        }
}

// ---------------- flash kernel: AC(HMMA) + shifted BD + online softmax + PV ----------------
__global__ __launch_bounds__(256) void flash_kernel()
{
    extern __shared__ char smem[];
    const uint32_t su = smem_to_u32(smem);
    constexpr int OFF_QWH = 0, OFF_QWL = 16384;
    constexpr int OFF_K = 32768;          // two stages of 32768 (hi | lo 16384)
    constexpr int OFF_VH = 98304;         // 2 chunks * 8192
    constexpr int OFF_VL = 114688;
    constexpr int OFF_PH = 131072;        // 2 chunks * 16384
    constexpr int OFF_PL = 163840;
    constexpr int OFF_RA = 196608;
    constexpr int OFF_RB = 197632;

    const int tid = threadIdx.x;
    const int lane = tid & 31, warp = tid >> 5;
    const int wm = warp & 3, wn = warp >> 2;
    const int bn = blockIdx.z;
    const int it = 7 - blockIdx.x;        // heavy tiles first
    const int i0 = it * 128;

    const __nv_bfloat16* qw = g_qwbf + (size_t)bn * QLEN * 128;
    const __nv_bfloat16* kb = g_kbf + (size_t)bn * QLEN * 128;
    const __nv_bfloat16* vt = g_vtbf + (size_t)bn * DH * 2048;
    const float* bdb = g_BD + (size_t)bn * QLEN * QLEN;
    float* redA = (float*)(smem + OFF_RA);
    float* redB = (float*)(smem + OFF_RB);

    // preload QW hi/lo + K tile 0 (one cp.async group)
#pragma unroll
    for (int i = 0; i < 4; i++) {
        int c = tid + i * 256, row = c >> 3, q = c & 7;
        uint32_t sw = SWZ128(row * 128 + q * 16);
        const __nv_bfloat16* gp = qw + (size_t)(i0 + row) * 128 + q * 8;
        cp_async16(su + OFF_QWH + sw, gp);
        cp_async16(su + OFF_QWL + sw, gp + 64);
    }
#pragma unroll
    for (int i = 0; i < 4; i++) {
        int c = tid + i * 256, row = c >> 3, q = c & 7;
        uint32_t sw = SWZ128(row * 128 + q * 16);
        const __nv_bfloat16* gp = kb + (size_t)row * 128 + q * 8;
        cp_async16(su + OFF_K + sw, gp);
        cp_async16(su + OFF_K + 16384 + sw, gp + 64);
    }
    cp_commit();

    float acc_o[2][4][4];
#pragma unroll
    for (int mt = 0; mt < 2; mt++)
#pragma unroll
        for (int nt = 0; nt < 4; nt++)
#pragma unroll
            for (int u = 0; u < 4; u++) acc_o[mt][nt][u] = 0.f;
    float m_old[4], l_run[4];
#pragma unroll
    for (int i = 0; i < 4; i++) { m_old[i] = NEGINF; l_run[i] = 0.f; }

    for (int jt = 0; jt <= it; jt++) {
        const int s = jt & 1;
        const int j0 = jt * 128;
        const bool more = (jt < it);
        cp_wait<0>();
        __syncthreads();

        // issue V_jt (group), then next K (group)
#pragma unroll
        for (int i = 0; i < 8; i++) {
            int c = tid + i * 256;
            int q = c & 7, row = (c >> 3) & 63, ch = (c >> 9) & 1, hf = c >> 10;
            uint32_t sw = SWZ128(row * 128 + q * 16) + ch * 8192;
            const __nv_bfloat16* gp = vt + (size_t)row * 2048 + hf * 1024 + j0 + ch * 64 + q * 8;
            cp_async16(su + (hf ? OFF_VL : OFF_VH) + sw, gp);
        }
        cp_commit();
        if (more) {
            int j0n = j0 + 128;
#pragma unroll
            for (int i = 0; i < 4; i++) {
                int c = tid + i * 256, row = c >> 3, q = c & 7;
                uint32_t sw = SWZ128(row * 128 + q * 16);
                const __nv_bfloat16* gp = kb + (size_t)(j0n + row) * 128 + q * 8;
                cp_async16(su + OFF_K + (s ^ 1) * 32768 + sw, gp);
                cp_async16(su + OFF_K + (s ^ 1) * 32768 + 16384 + sw, gp + 64);
            }
            cp_commit();
        }

        // ---- S = qw @ k^T (3-term) ----
        float accS[2][8][4];
#pragma unroll
        for (int mt = 0; mt < 2; mt++)
#pragma unroll
            for (int nt = 0; nt < 8; nt++)
#pragma unroll
                for (int u = 0; u < 4; u++) accS[mt][nt][u] = 0.f;

        const uint32_t ah_ = su + OFF_QWH, al_ = su + OFF_QWL;
        const uint32_t bh_ = su + OFF_K + s * 32768, bl_ = bh_ + 16384;
#pragma unroll
        for (int kk = 0; kk < 4; kk++) {
            const int seg = kk * 32 + (lane >> 4) * 16;
            uint32_t afh[2][4], afl[2][4], bfh[8][2], bfl[8][2];
#pragma unroll
            for (int mt = 0; mt < 2; mt++) {
                int sw = SWZ128((wm * 32 + mt * 16 + (lane & 15)) * 128 + seg);
                ldm_x4(afh[mt], ah_ + sw);
                ldm_x4(afl[mt], al_ + sw);
            }
#pragma unroll
            for (int p = 0; p < 4; p++) {
                int sw = SWZ128((wn * 64 + p * 16 + (lane & 15)) * 128 + seg);
                uint32_t r[4];
                ldm_x4(r, bh_ + sw);
                bfh[2 * p][0] = r[0]; bfh[2 * p][1] = r[2];
                bfh[2 * p + 1][0] = r[1]; bfh[2 * p + 1][1] = r[3];
                ldm_x4(r, bl_ + sw);
                bfl[2 * p][0] = r[0]; bfl[2 * p][1] = r[2];
                bfl[2 * p + 1][0] = r[1]; bfl[2 * p + 1][1] = r[3];
            }
#pragma unroll
            for (int mt = 0; mt < 2; mt++)
#pragma unroll
                for (int nt = 0; nt < 8; nt++)
                    mma16816(accS[mt][nt], afh[mt], bfh[nt]);
#pragma unroll
            for (int mt = 0; mt < 2; mt++)
#pragma unroll
                for (int nt = 0; nt < 8; nt++)
                    mma16816(accS[mt][nt], afl[mt], bfh[nt]);
#pragma unroll
            for (int mt = 0; mt < 2; mt++)
#pragma unroll
                for (int nt = 0; nt < 8; nt++)
                    mma16816(accS[mt][nt], afh[mt], bfl[nt]);
        }

        // ---- + shifted BD, causal mask (qw/qr pre-scaled by 0.125) ----
#pragma unroll
        for (int mt = 0; mt < 2; mt++)
#pragma unroll
            for (int hf = 0; hf < 2; hf++) {
                int row_l = wm * 32 + mt * 16 + (lane >> 2) + hf * 8;
                int gi = i0 + row_l;
                const float* bdrow = bdb + (size_t)gi * 1024 + (1023 - gi) + j0;
#pragma unroll
                for (int nt = 0; nt < 8; nt++)
#pragma unroll
                    for (int e = 0; e < 2; e++) {
                        int col = wn * 64 + nt * 8 + (lane & 3) * 2 + e;
                        int gj = j0 + col;
                        float v = (gj <= gi) ? (accS[mt][nt][hf * 2 + e] + bdrow[col]) : NEGINF;
                        accS[mt][nt][hf * 2 + e] = v;
                    }
            }

        // ---- online softmax: row max ----
        float m_new[4], alpha[4];
#pragma unroll
        for (int mt = 0; mt < 2; mt++)
#pragma unroll
            for (int hf = 0; hf < 2; hf++) {
                float mx = NEGINF;
#pragma unroll
                for (int nt = 0; nt < 8; nt++)
                    mx = fmaxf(mx, fmaxf(accS[mt][nt][hf * 2], accS[mt][nt][hf * 2 + 1]));
                mx = fmaxf(mx, __shfl_xor_sync(0xffffffffu, mx, 1));
                mx = fmaxf(mx, __shfl_xor_sync(0xffffffffu, mx, 2));
                if ((lane & 3) == 0) redA[wn * 128 + wm * 32 + mt * 16 + (lane >> 2) + hf * 8] = mx;
                m_new[mt * 2 + hf] = mx;
            }
        __syncthreads();
#pragma unroll
        for (int mt = 0; mt < 2; mt++)
#pragma unroll
            for (int hf = 0; hf < 2; hf++) {
                int row_l = wm * 32 + mt * 16 + (lane >> 2) + hf * 8;
                int idx = mt * 2 + hf;
                float comb = fmaxf(redA[row_l], redA[128 + row_l]);
                float mn = fmaxf(m_old[idx], comb);
                alpha[idx] = __expf(m_old[idx] - mn);
                m_new[idx] = mn;
                m_old[idx] = mn;                     // advance softmax state
            }

        // ---- p = exp(s - m), row sums ----
#pragma unroll
        for (int mt = 0; mt < 2; mt++)
#pragma unroll
            for (int hf = 0; hf < 2; hf++) {
                int idx = mt * 2 + hf;
                float ssum = 0.f;
#pragma unroll
                for (int nt = 0; nt < 8; nt++)
#pragma unroll
                    for (int e = 0; e < 2; e++) {
                        float p = __expf(accS[mt][nt][hf * 2 + e] - m_new[idx]);
                        accS[mt][nt][hf * 2 + e] = p;
                        ssum += p;
                    }
                ssum += __shfl_xor_sync(0xffffffffu, ssum, 1);
                ssum += __shfl_xor_sync(0xffffffffu, ssum, 2);
                if ((lane & 3) == 0) redB[wn * 128 + wm * 32 + mt * 16 + (lane >> 2) + hf * 8] = ssum;
            }
        __syncthreads();
#pragma unroll
        for (int mt = 0; mt < 2; mt++)
#pragma unroll
            for (int hf = 0; hf < 2; hf++) {
                int row_l = wm * 32 + mt * 16 + (lane >> 2) + hf * 8;
                int idx = mt * 2 + hf;
                l_run[idx] = l_run[idx] * alpha[idx] + redB[row_l] + redB[128 + row_l];
            }

        // ---- rescale acc_o ----
#pragma unroll
        for (int mt = 0; mt < 2; mt++)
#pragma unroll
            for (int nt = 0; nt < 4; nt++)
#pragma unroll
                for (int u = 0; u < 4; u++) acc_o[mt][nt][u] *= alpha[mt * 2 + (u >> 1)];

        // ---- store P (split bf16, two 64-col chunks; chunk = wn) ----
#pragma unroll
        for (int mt = 0; mt < 2; mt++)
#pragma unroll
            for (int hf = 0; hf < 2; hf++) {
                int row_l = wm * 32 + mt * 16 + (lane >> 2) + hf * 8;
#pragma unroll
                for (int nt = 0; nt < 8; nt++) {
                    float v0 = accS[mt][nt][hf * 2], v1 = accS[mt][nt][hf * 2 + 1];
                    __nv_bfloat16 h0, l0, h1, l1;
                    split2(v0, h0, l0);
                    split2(v1, h1, l1);
                    uint32_t off = SWZ128(row_l * 128 + (nt * 8 + (lane & 3) * 2) * 2);
                    *(__nv_bfloat162*)(smem + OFF_PH + wn * 16384 + off) = __nv_bfloat162(h0, h1);
                    *(__nv_bfloat162*)(smem + OFF_PL + wn * 16384 + off) = __nv_bfloat162(l0, l1);
                }
            }
        if (more) cp_wait<1>(); else cp_wait<0>();
        __syncthreads();   // P + V visible

        // ---- PV: acc_o += P @ V ----
#pragma unroll
        for (int kk = 0; kk < 8; kk++) {
            const int ch = kk >> 2;
            const int seg = (kk & 3) * 32 + (lane >> 4) * 16;
            uint32_t pah[2][4], pal[2][4], vbh[4][2], vbl[4][2];
#pragma unroll
            for (int mt = 0; mt < 2; mt++) {
                int sw = SWZ128((wm * 32 + mt * 16 + (lane & 15)) * 128 + seg);
                ldm_x4(pah[mt], su + OFF_PH + ch * 16384 + sw);
                ldm_x4(pal[mt], su + OFF_PL + ch * 16384 + sw);
            }
#pragma unroll
            for (int p = 0; p < 2; p++) {
                int sw = SWZ128((wn * 32 + p * 16 + (lane & 15)) * 128 + seg);
                uint32_t r[4];
                ldm_x4(r, su + OFF_VH + ch * 8192 + sw);
                vbh[2 * p][0] = r[0]; vbh[2 * p][1] = r[2];
                vbh[2 * p + 1][0] = r[1]; vbh[2 * p + 1][1] = r[3];
                ldm_x4(r, su + OFF_VL + ch * 8192 + sw);
                vbl[2 * p][0] = r[0]; vbl[2 * p][1] = r[2];
                vbl[2 * p + 1][0] = r[1]; vbl[2 * p + 1][1] = r[3];
            }
#pragma unroll
            for (int mt = 0; mt < 2; mt++)
#pragma unroll
                for (int nt = 0; nt < 4; nt++)
                    mma16816(acc_o[mt][nt], pah[mt], vbh[nt]);
#pragma unroll
            for (int mt = 0; mt < 2; mt++)
#pragma unroll
                for (int nt = 0; nt < 4; nt++)
                    mma16816(acc_o[mt][nt], pal[mt], vbh[nt]);
#pragma unroll
            for (int mt = 0; mt < 2; mt++)
#pragma unroll
                for (int nt = 0; nt < 4; nt++)
                    mma16816(acc_o[mt][nt], pah[mt], vbl[nt]);
        }
        __syncthreads();   // V/P free for next iter
        (void)ah_; (void)al_;
    }

    // ---- epilogue: vec = acc_o / l, split bf16 into g_vecbf ----
    const int b = bn >> 4, n = bn & 15;
    float inv[4];
#pragma unroll
    for (int i = 0; i < 4; i++) inv[i] = 1.f / l_run[i];
#pragma unroll
    for (int mt = 0; mt < 2; mt++)
#pragma unroll
        for (int nt = 0; nt < 4; nt++)
#pragma unroll
            for (int hf = 0; hf < 2; hf++) {
                int row_l = wm * 32 + mt * 16 + (lane >> 2) + hf * 8;
                int gi = i0 + row_l;
                int d0 = wn * 32 + nt * 8 + (lane & 3) * 2;
                float v0 = acc_o[mt][nt][hf * 2] * inv[mt * 2 + hf];
                float v1 = acc_o[mt][nt][hf * 2 + 1] * inv[mt * 2 + hf];
                __nv_bfloat16 h0, l0, h1, l1;
                split2(v0, h0, l0);
                split2(v1, h1, l1);
                size_t orow = (size_t)(gi * 4 + b) * 2048 + n * 64 + d0;
                *(__nv_bfloat162*)&g_vecbf[orow] = __nv_bfloat162(h0, h1);
                *(__nv_bfloat162*)&g_vecbf[orow + 1024] = __nv_bfloat162(l0, l1);
            }
}

// ---------------- split / transpose / pack kernels ----------------
__global__ void split_kernel(const float* __restrict__ X, __nv_bfloat16* __restrict__ Y, int cols)
{
    int idx = blockIdx.x * 256 + threadIdx.x;
    int row = idx / cols, col = idx - row * cols;
    __nv_bfloat16 h, l;
    split2(X[idx], h, l);
    Y[(size_t)row * 2 * cols + col] = h;
    Y[(size_t)row * 2 * cols + cols + col] = l;
}

__global__ __launch_bounds__(256) void tsplit_kernel(const float* __restrict__ X,
                                                     __nv_bfloat16* __restrict__ Y, int N, int K)
{
    __shared__ float sm[64][65];
    int k0 = blockIdx.x * 64, n0 = blockIdx.y * 64;
    int tid = threadIdx.x;
    for (int e = tid; e < 4096; e += 256) {
        int r = e >> 6, c = e & 63;
        sm[c][r] = X[(size_t)(k0 + r) * N + n0 + c];
    }
    __syncthreads();
    for (int e = tid; e < 4096; e += 256) {
        int r = e >> 6, c = e & 63;
        __nv_bfloat16 h, l;
        split2(sm[r][c], h, l);
        Y[(size_t)(n0 + r) * 2 * K + k0 + c] = h;
        Y[(size_t)(n0 + r) * 2 * K + K + k0 + c] = l;
    }
}

__global__ void pack_qk_kernel(const float* __restrict__ rwb, const float* __restrict__ rrb)
{
    int idx = blockIdx.x * 256 + threadIdx.x;
    int d = idx & 63, i = (idx >> 6) & 1023, bn = idx >> 16;
    int b = bn >> 4, n = bn & 15;
    size_t hbase = (size_t)(i * 4 + b) * 3072 + n * 64 + d;
    float q = g_heads[hbase];
    float k = g_heads[hbase + 1024];
    size_t o = ((size_t)bn * QLEN + i) * 128 + d;
    __nv_bfloat16 h, l;
    split2((q + rwb[n * 64 + d]) * 0.125f, h, l);
    g_qwbf[o] = h; g_qwbf[o + 64] = l;
    split2((q + rrb[n * 64 + d]) * 0.125f, h, l);
    g_qrbf[o] = h; g_qrbf[o + 64] = l;
    split2(k, h, l);
    g_kbf[o] = h; g_kbf[o + 64] = l;
}

__global__ void pack_rk_kernel()
{
    int idx = blockIdx.x * 256 + threadIdx.x;
    int d = idx & 63, m = (idx >> 6) & 1023, n = idx >> 16;
    __nv_bfloat16 h, l;
    split2(g_rk[(size_t)m * 1024 + n * 64 + d], h, l);
    size_t o = ((size_t)n * QLEN + m) * 128 + d;
    g_rkbf[o] = h; g_rkbf[o + 64] = l;
}

__global__ __launch_bounds__(256) void pack_vt_kernel()
{
    __shared__ float sm[64][65];
    int bn = blockIdx.y, b = bn >> 4, n = bn & 15;
    int j0 = blockIdx.x * 64;
    int tid = threadIdx.x;
    for (int e = tid; e < 4096; e += 256) {
        int jj = e >> 6, d = e & 63;
        sm[d][jj] = g_heads[(size_t)((j0 + jj) * 4 + b) * 3072 + 2048 + n * 64 + d];
    }
    __syncthreads();
    for (int e = tid; e < 4096; e += 256) {
        int d = e >> 6, jj = e & 63;
        __nv_bfloat16 h, l;
        split2(sm[d][jj], h, l);
        g_vtbf[((size_t)bn * 64 + d) * 2048 + j0 + jj] = h;
        g_vtbf[((size_t)bn * 64 + d) * 2048 + 1024 + j0 + jj] = l;
    }
}

// ---------------- residual + layernorm ----------------
__global__ __launch_bounds__(256) void ln_kernel(
    const float* __restrict__ w, const float* __restrict__ gamma,
    const float* __restrict__ beta, float* __restrict__ out)
{
    int row = blockIdx.x;
    const float* wr = w + (size_t)row * DM;
    const float* ar = g_attn + (size_t)row * DM;
    int tid = threadIdx.x;

    float x[4];
    float s = 0.f, s2 = 0.f;
#pragma unroll
    for (int u = 0; u < 4; u++) {
        int c = tid + u * 256;
        x[u] = wr[c] + ar[c];
        s += x[u];
        s2 += x[u] * x[u];
    }
    __shared__ float rs[256], rs2[256];
    rs[tid] = s; rs2[tid] = s2;
    __syncthreads();
    for (int t = 128; t > 0; t >>= 1) {
        if (tid < t) { rs[tid] += rs[tid + t]; rs2[tid] += rs2[tid + t]; }
        __syncthreads();
    }
    float mu = rs[0] * (1.f / DM);
    float var = rs2[0] * (1.f / DM) - mu * mu;
    float rstd = rsqrtf(var + 1e-5f);
#pragma unroll
    for (int u = 0; u < 4; u++) {
        int c = tid + u * 256;
        out[(size_t)row * DM + c] = (x[u] - mu) * rstd * gamma[c] + beta[c];
    }
}

// ---------------- launch ----------------
extern "C" void kernel_launch(void* const* d_in, const int* in_sizes, int n_in,
                              void* d_out, int out_size)
{
    const float* w     = (const float*)d_in[0];
    const float* r     = (const float*)d_in[1];
    const float* rwb   = (const float*)d_in[2];
    const float* rrb   = (const float*)d_in[3];
    const float* W_qkv = (const float*)d_in[5];
    const float* W_r   = (const float*)d_in[6];
    const float* W_o   = (const float*)d_in[7];
    const float* gamma = (const float*)d_in[8];
    const float* beta  = (const float*)d_in[9];
    float* out = (float*)d_out;

    float *p_heads, *p_rk, *p_BD, *p_attn;
    __nv_bfloat16 *p_wbf, *p_rbf, *p_qkvt, *p_wrt, *p_wot;
    __nv_bfloat16 *p_qwbf, *p_qrbf, *p_kbf, *p_rkbf, *p_vtbf, *p_vecbf;
    cudaGetSymbolAddress((void**)&p_heads, g_heads);
    cudaGetSymbolAddress((void**)&p_rk, g_rk);
    cudaGetSymbolAddress((void**)&p_BD, g_BD);
    cudaGetSymbolAddress((void**)&p_attn, g_attn);
    cudaGetSymbolAddress((void**)&p_wbf, g_wbf);
    cudaGetSymbolAddress((void**)&p_rbf, g_rbf);
    cudaGetSymbolAddress((void**)&p_qkvt, g_qkvt);
    cudaGetSymbolAddress((void**)&p_wrt, g_wrt);
    cudaGetSymbolAddress((void**)&p_wot, g_wot);
    cudaGetSymbolAddress((void**)&p_qwbf, g_qwbf);
    cudaGetSymbolAddress((void**)&p_qrbf, g_qrbf);
    cudaGetSymbolAddress((void**)&p_kbf, g_kbf);
    cudaGetSymbolAddress((void**)&p_rkbf, g_rkbf);
    cudaGetSymbolAddress((void**)&p_vtbf, g_vtbf);
    cudaGetSymbolAddress((void**)&p_vecbf, g_vecbf);

    cudaFuncSetAttribute(mma_gemm2<128, 128>, cudaFuncAttributeMaxDynamicSharedMemorySize, 131072);
    cudaFuncSetAttribute(flash_kernel, cudaFuncAttributeMaxDynamicSharedMemorySize, 198656);

    const int FULLMASK = 0x7FFFFFFF;
    constexpr int SM128 = 131072;

    split_kernel<<<4096 * 1024 / 256, 256>>>(w, p_wbf, 1024);                 // 0
    tsplit_kernel<<<dim3(16, 48), 256>>>(W_qkv, p_qkvt, 3072, 1024);          // 1

    mma_gemm2<128, 128><<<dim3(24, 32, 1), 256, SM128>>>(                     // 2: heads
        p_wbf, p_qkvt, p_heads, 1024, 2048, 2048, 3072, 0, 0, 0, 0, FULLMASK);

    split_kernel<<<1024 * 1024 / 256, 256>>>(r, p_rbf, 1024);                 // 3
    tsplit_kernel<<<dim3(16, 16), 256>>>(W_r, p_wrt, 1024, 1024);             // 4

    mma_gemm2<128, 128><<<dim3(8, 8, 1), 256, SM128>>>(                       // 5: r_k
        p_rbf, p_wrt, p_rk, 1024, 2048, 2048, 1024, 0, 0, 0, 0, FULLMASK);

    pack_qk_kernel<<<BN_TOT * QLEN * DH / 256, 256>>>(rwb, rrb);              // 6
    pack_rk_kernel<<<NH * QLEN * DH / 256, 256>>>();                          // 7
    pack_vt_kernel<<<dim3(16, 64), 256>>>();                                  // 8

    // BDrel = qr @ rk^T (anti-tri tiles, B batch = head), pre-scaled 0.125
    mma_gemm2<128, 128><<<dim3(36, 1, BN_TOT), 256, SM128>>>(                 // 9
        p_qrbf, p_rkbf, p_BD, 64, 128, 128, 1024,
        (long long)QLEN * 128, (long long)QLEN * 128, (long long)QLEN * QLEN,
        2, 15);

    // fused AC + BD + softmax + PV
    flash_kernel<<<dim3(8, 1, BN_TOT), 256, 198656>>>();                      // 10

    tsplit_kernel<<<dim3(16, 16), 256>>>(W_o, p_wot, 1024, 1024);             // 11

    mma_gemm2<128, 128><<<dim3(8, 32, 1), 256, SM128>>>(                      // 12: attn
        p_vecbf, p_wot, p_attn, 1024, 2048, 2048, 1024, 0, 0, 0, 0, FULLMASK);

    ln_kernel<<<4096, 256>>>(w, gamma, beta, out);                            // 13
}